// round 5
// baseline (speedup 1.0000x reference)
#include <cuda_runtime.h>
#include <math.h>

// Fixed-shape problem: B=4, N=50000, E=800000, D=64
#define NN 50000
#define BB 4
#define DD 64
#define NR (NN * BB)          // 200000 rows
#define SCAN_B 196            // ceil(50000/256)
#define GEMM_B (NR / 64)      // 3125 blocks for gemm
#define FLAG_BIT 0x40000000

// Scratch (__device__ globals per allocation-free rule)
__device__ float4 g_xw[(size_t)NR * 16];        // linear output, (N,B,D) = 51.2 MB
__device__ float4 g_h1[(size_t)NR * 16];        // layer-1 activation, (N,B,D)
__device__ float  g_dis[NN];                    // rsqrt(deg+1)
__device__ int    g_deg[NN];                    // zero-init; re-zeroed each pass
__device__ int    g_off[NN + 1];                // CSR offsets (by target node)
__device__ int    g_cur[NN];                    // fill cursors
__device__ unsigned long long g_edge[800000];   // packed (src, nrm)
__device__ int    g_pub[SCAN_B];                // lookback publications

// ---------------------------------------------------------------------------
__global__ __launch_bounds__(256) void count_k(const int* __restrict__ ei, int E) {
    const int t = blockIdx.x * blockDim.x + threadIdx.x;
    if (blockIdx.x == 0 && threadIdx.x < SCAN_B) g_pub[threadIdx.x] = 0;
    const int e4 = t * 4;
    if (e4 + 4 <= E) {
        const int4 c = __ldg((const int4*)(ei + E) + t);
        atomicAdd(&g_deg[c.x], 1);
        atomicAdd(&g_deg[c.y], 1);
        atomicAdd(&g_deg[c.z], 1);
        atomicAdd(&g_deg[c.w], 1);
    } else {
        for (int e = e4; e < E; e++) atomicAdd(&g_deg[ei[E + e]], 1);
    }
}

// single-pass exclusive scan (decoupled lookback); emits g_dis, re-zeroes g_deg
__global__ __launch_bounds__(256) void scan_k(int E) {
    __shared__ int sh[256];
    __shared__ int s_prefix;
    const int tid = threadIdx.x;
    const int b   = blockIdx.x;
    const int idx = b * 256 + tid;

    int v = 0;
    if (idx < NN) {
        v = g_deg[idx];
        g_deg[idx] = 0;
        g_dis[idx] = rsqrtf((float)(v + 1));
    }
    sh[tid] = v;
    __syncthreads();
#pragma unroll
    for (int o = 1; o < 256; o <<= 1) {
        int t2 = (tid >= o) ? sh[tid - o] : 0;
        __syncthreads();
        sh[tid] += t2;
        __syncthreads();
    }
    const int incl = sh[tid];
    const int total = sh[255];

    if (tid == 0) {
        s_prefix = 0;
        __threadfence();
        atomicExch(&g_pub[b], total | FLAG_BIT);
        if (b == 0) g_off[NN] = E;
    }
    __syncthreads();

    if (tid < b) {
        int p;
        do { p = atomicAdd(&g_pub[tid], 0); } while (!(p & FLAG_BIT));
        atomicAdd(&s_prefix, p & ~FLAG_BIT);
    }
    __syncthreads();

    if (idx < NN) {
        const int off = s_prefix + incl - v;
        g_off[idx] = off;
        g_cur[idx] = off;
    }
}

// ---------------------------------------------------------------------------
// GEMM body: 64 rows x 64 cols per 256-thread block, 2x8 register tile.
// ---------------------------------------------------------------------------
template <bool XBND>
__device__ __forceinline__ void gemm_body(const float* __restrict__ x,
                                          const float* __restrict__ W,
                                          int blk) {
    __shared__ __align__(16) float Ws[64 * 68];
    __shared__ float xs[64 * 65];
    const int tid = threadIdx.x;

    for (int i = tid; i < 4096; i += 256)
        Ws[(i >> 6) * 68 + (i & 63)] = W[i];

    const int base = blk * 64;
    {
        const int rl = tid >> 6, d = tid & 63;
#pragma unroll
        for (int g = 0; g < 64; g += 4) {
            const int rr = base + g + rl;
            float v;
            if (XBND) {
                const int n = rr >> 2, bb = rr & 3;
                v = x[((size_t)bb * NN + n) * DD + d];
            } else {
                v = x[(size_t)rr * DD + d];
            }
            xs[(g + rl) * 65 + d] = v;
        }
    }
    __syncthreads();

    const int r2 = (tid >> 3) * 2;
    const int c8 = (tid & 7) * 8;
    float acc[2][8];
#pragma unroll
    for (int i = 0; i < 2; i++)
#pragma unroll
        for (int j = 0; j < 8; j++) acc[i][j] = 0.0f;

#pragma unroll 8
    for (int k = 0; k < 64; k++) {
        const float a0 = xs[r2 * 65 + k];
        const float a1 = xs[(r2 + 1) * 65 + k];
        const float4 w0 = *(const float4*)&Ws[k * 68 + c8];
        const float4 w1 = *(const float4*)&Ws[k * 68 + c8 + 4];
        acc[0][0] = fmaf(a0, w0.x, acc[0][0]);
        acc[0][1] = fmaf(a0, w0.y, acc[0][1]);
        acc[0][2] = fmaf(a0, w0.z, acc[0][2]);
        acc[0][3] = fmaf(a0, w0.w, acc[0][3]);
        acc[0][4] = fmaf(a0, w1.x, acc[0][4]);
        acc[0][5] = fmaf(a0, w1.y, acc[0][5]);
        acc[0][6] = fmaf(a0, w1.z, acc[0][6]);
        acc[0][7] = fmaf(a0, w1.w, acc[0][7]);
        acc[1][0] = fmaf(a1, w0.x, acc[1][0]);
        acc[1][1] = fmaf(a1, w0.y, acc[1][1]);
        acc[1][2] = fmaf(a1, w0.z, acc[1][2]);
        acc[1][3] = fmaf(a1, w0.w, acc[1][3]);
        acc[1][4] = fmaf(a1, w1.x, acc[1][4]);
        acc[1][5] = fmaf(a1, w1.y, acc[1][5]);
        acc[1][6] = fmaf(a1, w1.z, acc[1][6]);
        acc[1][7] = fmaf(a1, w1.w, acc[1][7]);
    }

    float* outp = (float*)g_xw;
#pragma unroll
    for (int i = 0; i < 2; i++) {
        const size_t row = (size_t)(base + r2 + i);
        *(float4*)&outp[row * DD + c8]     = make_float4(acc[i][0], acc[i][1], acc[i][2], acc[i][3]);
        *(float4*)&outp[row * DD + c8 + 4] = make_float4(acc[i][4], acc[i][5], acc[i][6], acc[i][7]);
    }
}

__device__ __forceinline__ void fill_body(const int* __restrict__ ei, int E, int blk) {
    const int e = blk * 256 + threadIdx.x;
    if (e >= E) return;
    const int r = ei[e];
    const int c = ei[E + e];
    const int pos = atomicAdd(&g_cur[c], 1);
    const float nm = g_dis[r] * g_dis[c];
    g_edge[pos] = (unsigned long long)(unsigned int)r |
                  ((unsigned long long)__float_as_uint(nm) << 32);
}

__global__ __launch_bounds__(256) void gemmfill_k(const float* __restrict__ x,
                                                  const float* __restrict__ W,
                                                  const int* __restrict__ ei, int E) {
    if (blockIdx.x < GEMM_B) gemm_body<true>(x, W, blockIdx.x);
    else                     fill_body(ei, E, blockIdx.x - GEMM_B);
}

__global__ __launch_bounds__(256) void gemm2_k(const float* __restrict__ x,
                                               const float* __restrict__ W) {
    gemm_body<false>(x, W, blockIdx.x);
}

// ---------------------------------------------------------------------------
// Aggregation: WARP per node. Lane owns float4 slices (2*lane, 2*lane+1).
// Software-pipelined edge-record prefetch; batched value loads (MLP ~12).
// ---------------------------------------------------------------------------
__device__ __forceinline__ void fma4(float4& a, const float4 v, const float n) {
    a.x = fmaf(v.x, n, a.x);
    a.y = fmaf(v.y, n, a.y);
    a.z = fmaf(v.z, n, a.z);
    a.w = fmaf(v.w, n, a.w);
}

__device__ __forceinline__ void edge_batch4(const float4* __restrict__ xw, int L2,
                                            unsigned long long e0, unsigned long long e1,
                                            unsigned long long e2, unsigned long long e3,
                                            float4& A0, float4& A1) {
    const size_t s0 = (size_t)(unsigned int)(e0 & 0xffffffffu) * 64 + L2;
    const size_t s1 = (size_t)(unsigned int)(e1 & 0xffffffffu) * 64 + L2;
    const size_t s2 = (size_t)(unsigned int)(e2 & 0xffffffffu) * 64 + L2;
    const size_t s3 = (size_t)(unsigned int)(e3 & 0xffffffffu) * 64 + L2;
    const float4 v00 = __ldg(xw + s0),     v01 = __ldg(xw + s0 + 1);
    const float4 v10 = __ldg(xw + s1),     v11 = __ldg(xw + s1 + 1);
    const float4 v20 = __ldg(xw + s2),     v21 = __ldg(xw + s2 + 1);
    const float4 v30 = __ldg(xw + s3),     v31 = __ldg(xw + s3 + 1);
    const float n0 = __uint_as_float((unsigned int)(e0 >> 32));
    const float n1 = __uint_as_float((unsigned int)(e1 >> 32));
    const float n2 = __uint_as_float((unsigned int)(e2 >> 32));
    const float n3 = __uint_as_float((unsigned int)(e3 >> 32));
    fma4(A0, v00, n0); fma4(A1, v01, n0);
    fma4(A0, v10, n1); fma4(A1, v11, n1);
    fma4(A0, v20, n2); fma4(A1, v21, n2);
    fma4(A0, v30, n3); fma4(A1, v31, n3);
}

template <bool FINAL>
__global__ __launch_bounds__(256) void agg_k(const float* __restrict__ bias,
                                             float* __restrict__ dst) {
    const int node = blockIdx.x * 8 + (threadIdx.x >> 5);
    const int lane = threadIdx.x & 31;
    if (node >= NN) return;

    const float4* __restrict__ xw = g_xw;
    const int L2 = lane * 2;                       // float4 slice index
    const size_t self = (size_t)node * 64 + L2;

    const float dn = g_dis[node];
    const float sl = dn * dn;
    float4 A0 = __ldg(xw + self);
    float4 A1 = __ldg(xw + self + 1);
    A0.x *= sl; A0.y *= sl; A0.z *= sl; A0.w *= sl;
    A1.x *= sl; A1.y *= sl; A1.z *= sl; A1.w *= sl;

    int j = g_off[node];
    const int end = g_off[node + 1];

    unsigned long long e0 = 0, e1 = 0, e2 = 0, e3 = 0;
    if (j + 4 <= end) {
        e0 = __ldg(g_edge + j);
        e1 = __ldg(g_edge + j + 1);
        e2 = __ldg(g_edge + j + 2);
        e3 = __ldg(g_edge + j + 3);
    }
    while (j + 8 <= end) {
        const unsigned long long f0 = __ldg(g_edge + j + 4);
        const unsigned long long f1 = __ldg(g_edge + j + 5);
        const unsigned long long f2 = __ldg(g_edge + j + 6);
        const unsigned long long f3 = __ldg(g_edge + j + 7);
        edge_batch4(xw, L2, e0, e1, e2, e3, A0, A1);
        e0 = f0; e1 = f1; e2 = f2; e3 = f3;
        j += 4;
    }
    if (j + 4 <= end) {
        edge_batch4(xw, L2, e0, e1, e2, e3, A0, A1);
        j += 4;
    }
    // tail (<=3): batch the loads
    {
        const int rem = end - j;
        if (rem > 0) {
            const unsigned long long t0 = __ldg(g_edge + j);
            const unsigned long long t1 = (rem > 1) ? __ldg(g_edge + j + 1) : 0;
            const unsigned long long t2 = (rem > 2) ? __ldg(g_edge + j + 2) : 0;
            {
                const size_t s = (size_t)(unsigned int)(t0 & 0xffffffffu) * 64 + L2;
                const float4 v0 = __ldg(xw + s), v1 = __ldg(xw + s + 1);
                const float nm = __uint_as_float((unsigned int)(t0 >> 32));
                fma4(A0, v0, nm); fma4(A1, v1, nm);
            }
            if (rem > 1) {
                const size_t s = (size_t)(unsigned int)(t1 & 0xffffffffu) * 64 + L2;
                const float4 v0 = __ldg(xw + s), v1 = __ldg(xw + s + 1);
                const float nm = __uint_as_float((unsigned int)(t1 >> 32));
                fma4(A0, v0, nm); fma4(A1, v1, nm);
            }
            if (rem > 2) {
                const size_t s = (size_t)(unsigned int)(t2 & 0xffffffffu) * 64 + L2;
                const float4 v0 = __ldg(xw + s), v1 = __ldg(xw + s + 1);
                const float nm = __uint_as_float((unsigned int)(t2 >> 32));
                fma4(A0, v0, nm); fma4(A1, v1, nm);
            }
        }
    }

    const float4 bv0 = __ldg((const float4*)bias + (L2 & 15));
    const float4 bv1 = __ldg((const float4*)bias + ((L2 + 1) & 15));
    float4 o0, o1;
    o0.x = tanhf(A0.x + bv0.x); o0.y = tanhf(A0.y + bv0.y);
    o0.z = tanhf(A0.z + bv0.z); o0.w = tanhf(A0.w + bv0.w);
    o1.x = tanhf(A1.x + bv1.x); o1.y = tanhf(A1.y + bv1.y);
    o1.z = tanhf(A1.z + bv1.z); o1.w = tanhf(A1.w + bv1.w);

    if (FINAL) {
        const int f0 = L2, f1 = L2 + 1;
        ((float4*)dst)[((size_t)(f0 >> 4) * NN + node) * 16 + (f0 & 15)] = o0;
        ((float4*)dst)[((size_t)(f1 >> 4) * NN + node) * 16 + (f1 & 15)] = o1;
    } else {
        ((float4*)dst)[self]     = o0;
        ((float4*)dst)[self + 1] = o1;
    }
}

// ---------------------------------------------------------------------------
extern "C" void kernel_launch(void* const* d_in, const int* in_sizes, int n_in,
                              void* d_out, int out_size) {
    const float* h  = (const float*)d_in[1];
    const int*   ei = (const int*)d_in[2];
    const float* W1 = (const float*)d_in[3];
    const float* b1 = (const float*)d_in[4];
    const float* W2 = (const float*)d_in[5];
    const float* b2 = (const float*)d_in[6];
    float* out = (float*)d_out;

    const int E  = in_sizes[2] / 2;
    const int eB = (E + 255) / 256;
    const int cB = (E / 4 + 255) / 256 + 1;
    const int aB = (NN + 7) / 8;    // warp per node, 8 nodes/block

    count_k   <<<cB, 256>>>(ei, E);                       // 1
    scan_k    <<<SCAN_B, 256>>>(E);                       // 2
    gemmfill_k<<<GEMM_B + eB, 256>>>(h, W1, ei, E);       // 3
    agg_k<false><<<aB, 256>>>(b1, (float*)g_h1);          // 4  <- profiled
    gemm2_k   <<<GEMM_B, 256>>>((const float*)g_h1, W2);  // 5
    agg_k<true> <<<aB, 256>>>(b2, out);                   // 6
}

// round 6
// speedup vs baseline: 2.5197x; 2.5197x over previous
#include <cuda_runtime.h>
#include <cuda_fp16.h>
#include <math.h>

// Fixed-shape problem: B=4, N=50000, E=800000, D=64
#define NN 50000
#define BB 4
#define DD 64
#define NR (NN * BB)          // 200000 rows (node-major: row = node*4 + b)
#define SCAN_B 196            // ceil(50000/256)
#define GEMM_B (NR / 64)      // 3125 blocks
#define FLAG_BIT 0x40000000

// Scratch (__device__ globals per allocation-free rule)
// fp16 feature tables: 8 uint4 (= 64 halfs) per row; 32 uint4 per node chunk.
__device__ uint4  g_xwh[(size_t)NR * 8];        // linear output, fp16, 25.6 MB
__device__ uint4  g_h1h[(size_t)NR * 8];        // layer-1 activation, fp16, 25.6 MB
__device__ float  g_dis[NN];                    // rsqrt(deg+1)
__device__ int    g_deg[NN];                    // zero-init; re-zeroed each pass
__device__ int    g_off[NN + 1];                // CSR offsets (by target node)
__device__ int    g_cur[NN];                    // fill cursors
__device__ unsigned long long g_edge[800000];   // packed (src, nrm fp32)
__device__ int    g_pub[SCAN_B];                // lookback publications

// ---------------------------------------------------------------------------
__global__ __launch_bounds__(256) void count_k(const int* __restrict__ ei, int E) {
    const int t = blockIdx.x * blockDim.x + threadIdx.x;
    if (blockIdx.x == 0 && threadIdx.x < SCAN_B) g_pub[threadIdx.x] = 0;
    const int e4 = t * 4;
    if (e4 + 4 <= E) {
        const int4 c = __ldg((const int4*)(ei + E) + t);
        atomicAdd(&g_deg[c.x], 1);
        atomicAdd(&g_deg[c.y], 1);
        atomicAdd(&g_deg[c.z], 1);
        atomicAdd(&g_deg[c.w], 1);
    } else {
        for (int e = e4; e < E; e++) atomicAdd(&g_deg[ei[E + e]], 1);
    }
}

// single-pass exclusive scan (decoupled lookback); emits g_dis, re-zeroes g_deg
__global__ __launch_bounds__(256) void scan_k(int E) {
    __shared__ int sh[256];
    __shared__ int s_prefix;
    const int tid = threadIdx.x;
    const int b   = blockIdx.x;
    const int idx = b * 256 + tid;

    int v = 0;
    if (idx < NN) {
        v = g_deg[idx];
        g_deg[idx] = 0;
        g_dis[idx] = rsqrtf((float)(v + 1));
    }
    sh[tid] = v;
    __syncthreads();
#pragma unroll
    for (int o = 1; o < 256; o <<= 1) {
        int t2 = (tid >= o) ? sh[tid - o] : 0;
        __syncthreads();
        sh[tid] += t2;
        __syncthreads();
    }
    const int incl = sh[tid];
    const int total = sh[255];

    if (tid == 0) {
        s_prefix = 0;
        __threadfence();
        atomicExch(&g_pub[b], total | FLAG_BIT);
        if (b == 0) g_off[NN] = E;
    }
    __syncthreads();

    if (tid < b) {
        int p;
        do { p = atomicAdd(&g_pub[tid], 0); } while (!(p & FLAG_BIT));
        atomicAdd(&s_prefix, p & ~FLAG_BIT);
    }
    __syncthreads();

    if (idx < NN) {
        const int off = s_prefix + incl - v;
        g_off[idx] = off;
        g_cur[idx] = off;
    }
}

__global__ __launch_bounds__(256) void fill_k(const int* __restrict__ ei, int E) {
    const int e = blockIdx.x * 256 + threadIdx.x;
    if (e >= E) return;
    const int r = ei[e];        // source
    const int c = ei[E + e];    // target
    const int pos = atomicAdd(&g_cur[c], 1);
    const float nm = g_dis[r] * g_dis[c];
    g_edge[pos] = (unsigned long long)(unsigned int)r |
                  ((unsigned long long)__float_as_uint(nm) << 32);
}

// ---------------------------------------------------------------------------
// GEMM: 64 rows x 64 cols per 256-thread block, 2x8 register tile.
// MODE 0: x fp32 (B,N,D) (layer-1 h). MODE 1: x = g_h1h fp16 row-major.
// Output: g_xwh fp16.
// ---------------------------------------------------------------------------
template <int MODE>
__device__ __forceinline__ void gemm_body(const float* __restrict__ x,
                                          const float* __restrict__ W,
                                          int blk) {
    __shared__ __align__(16) float Ws[64 * 68];
    __shared__ float xs[64 * 65];
    const int tid = threadIdx.x;

    for (int i = tid; i < 4096; i += 256)
        Ws[(i >> 6) * 68 + (i & 63)] = W[i];

    const int base = blk * 64;
    if (MODE == 0) {
        const int rl = tid >> 6, d = tid & 63;
#pragma unroll
        for (int g = 0; g < 64; g += 4) {
            const int rr = base + g + rl;
            const int n = rr >> 2, bb = rr & 3;
            xs[(g + rl) * 65 + d] = x[((size_t)bb * NN + n) * DD + d];
        }
    } else {
        // 64 rows x 8 uint4 = 512 uint4; 2 iters of 256 threads
#pragma unroll
        for (int it = 0; it < 2; it++) {
            const int q = it * 256 + tid;
            const int row = q >> 3, u4 = q & 7;
            const uint4 u = __ldg(&g_h1h[(size_t)(base + row) * 8 + u4]);
            const __half2* hp = (const __half2*)&u;
            float* xp = &xs[row * 65 + u4 * 8];
            const float2 f0 = __half22float2(hp[0]);
            const float2 f1 = __half22float2(hp[1]);
            const float2 f2 = __half22float2(hp[2]);
            const float2 f3 = __half22float2(hp[3]);
            xp[0] = f0.x; xp[1] = f0.y; xp[2] = f1.x; xp[3] = f1.y;
            xp[4] = f2.x; xp[5] = f2.y; xp[6] = f3.x; xp[7] = f3.y;
        }
    }
    __syncthreads();

    const int r2 = (tid >> 3) * 2;
    const int c8 = (tid & 7) * 8;
    float acc[2][8];
#pragma unroll
    for (int i = 0; i < 2; i++)
#pragma unroll
        for (int j = 0; j < 8; j++) acc[i][j] = 0.0f;

#pragma unroll 8
    for (int k = 0; k < 64; k++) {
        const float a0 = xs[r2 * 65 + k];
        const float a1 = xs[(r2 + 1) * 65 + k];
        const float4 w0 = *(const float4*)&Ws[k * 68 + c8];
        const float4 w1 = *(const float4*)&Ws[k * 68 + c8 + 4];
        acc[0][0] = fmaf(a0, w0.x, acc[0][0]);
        acc[0][1] = fmaf(a0, w0.y, acc[0][1]);
        acc[0][2] = fmaf(a0, w0.z, acc[0][2]);
        acc[0][3] = fmaf(a0, w0.w, acc[0][3]);
        acc[0][4] = fmaf(a0, w1.x, acc[0][4]);
        acc[0][5] = fmaf(a0, w1.y, acc[0][5]);
        acc[0][6] = fmaf(a0, w1.z, acc[0][6]);
        acc[0][7] = fmaf(a0, w1.w, acc[0][7]);
        acc[1][0] = fmaf(a1, w0.x, acc[1][0]);
        acc[1][1] = fmaf(a1, w0.y, acc[1][1]);
        acc[1][2] = fmaf(a1, w0.z, acc[1][2]);
        acc[1][3] = fmaf(a1, w0.w, acc[1][3]);
        acc[1][4] = fmaf(a1, w1.x, acc[1][4]);
        acc[1][5] = fmaf(a1, w1.y, acc[1][5]);
        acc[1][6] = fmaf(a1, w1.z, acc[1][6]);
        acc[1][7] = fmaf(a1, w1.w, acc[1][7]);
    }

#pragma unroll
    for (int i = 0; i < 2; i++) {
        const size_t row = (size_t)(base + r2 + i);
        const __half2 p0 = __floats2half2_rn(acc[i][0], acc[i][1]);
        const __half2 p1 = __floats2half2_rn(acc[i][2], acc[i][3]);
        const __half2 p2 = __floats2half2_rn(acc[i][4], acc[i][5]);
        const __half2 p3 = __floats2half2_rn(acc[i][6], acc[i][7]);
        uint4 u;
        u.x = *(const unsigned int*)&p0;
        u.y = *(const unsigned int*)&p1;
        u.z = *(const unsigned int*)&p2;
        u.w = *(const unsigned int*)&p3;
        g_xwh[row * 8 + (tid & 7)] = u;
    }
}

__global__ __launch_bounds__(256) void gemm1_k(const float* __restrict__ x,
                                               const float* __restrict__ W) {
    gemm_body<0>(x, W, blockIdx.x);
}
__global__ __launch_bounds__(256) void gemm2_k(const float* __restrict__ W) {
    gemm_body<1>(nullptr, W, blockIdx.x);
}

// ---------------------------------------------------------------------------
// Aggregation: warp per node. Lane owns uint4 slice `lane` of the 32-uint4
// node chunk (= floats [lane*8, lane*8+8), i.e. b=lane/8, d=(lane%8)*8..+7).
// One 16B load per edge per lane; 4-edge batches, edge records prefetched.
// ---------------------------------------------------------------------------
__device__ __forceinline__ void fma_u4(float* A, const uint4 u, const float nm) {
    const __half2* hp = (const __half2*)&u;
    const float2 f0 = __half22float2(hp[0]);
    const float2 f1 = __half22float2(hp[1]);
    const float2 f2 = __half22float2(hp[2]);
    const float2 f3 = __half22float2(hp[3]);
    A[0] = fmaf(f0.x, nm, A[0]); A[1] = fmaf(f0.y, nm, A[1]);
    A[2] = fmaf(f1.x, nm, A[2]); A[3] = fmaf(f1.y, nm, A[3]);
    A[4] = fmaf(f2.x, nm, A[4]); A[5] = fmaf(f2.y, nm, A[5]);
    A[6] = fmaf(f3.x, nm, A[6]); A[7] = fmaf(f3.y, nm, A[7]);
}

template <bool FINAL>
__global__ __launch_bounds__(256) void agg_k(const float* __restrict__ bias,
                                             float* __restrict__ dst) {
    const int node = blockIdx.x * 8 + (threadIdx.x >> 5);
    const int lane = threadIdx.x & 31;
    if (node >= NN) return;

    const uint4* __restrict__ xw = g_xwh;
    float A[8];

    // self-loop term
    {
        const float dn = g_dis[node];
        const float sl = dn * dn;
        const uint4 u = __ldg(xw + (size_t)node * 32 + lane);
        const __half2* hp = (const __half2*)&u;
        const float2 f0 = __half22float2(hp[0]);
        const float2 f1 = __half22float2(hp[1]);
        const float2 f2 = __half22float2(hp[2]);
        const float2 f3 = __half22float2(hp[3]);
        A[0] = f0.x * sl; A[1] = f0.y * sl;
        A[2] = f1.x * sl; A[3] = f1.y * sl;
        A[4] = f2.x * sl; A[5] = f2.y * sl;
        A[6] = f3.x * sl; A[7] = f3.y * sl;
    }

    int j = g_off[node];
    const int end = g_off[node + 1];

    unsigned long long e0 = 0, e1 = 0, e2 = 0, e3 = 0;
    if (j + 4 <= end) {
        e0 = __ldg(g_edge + j);
        e1 = __ldg(g_edge + j + 1);
        e2 = __ldg(g_edge + j + 2);
        e3 = __ldg(g_edge + j + 3);
    }
    while (j + 8 <= end) {
        const unsigned long long f0 = __ldg(g_edge + j + 4);
        const unsigned long long f1 = __ldg(g_edge + j + 5);
        const unsigned long long f2 = __ldg(g_edge + j + 6);
        const unsigned long long f3 = __ldg(g_edge + j + 7);
        const uint4 v0 = __ldg(xw + (size_t)(unsigned int)(e0 & 0xffffffffu) * 32 + lane);
        const uint4 v1 = __ldg(xw + (size_t)(unsigned int)(e1 & 0xffffffffu) * 32 + lane);
        const uint4 v2 = __ldg(xw + (size_t)(unsigned int)(e2 & 0xffffffffu) * 32 + lane);
        const uint4 v3 = __ldg(xw + (size_t)(unsigned int)(e3 & 0xffffffffu) * 32 + lane);
        fma_u4(A, v0, __uint_as_float((unsigned int)(e0 >> 32)));
        fma_u4(A, v1, __uint_as_float((unsigned int)(e1 >> 32)));
        fma_u4(A, v2, __uint_as_float((unsigned int)(e2 >> 32)));
        fma_u4(A, v3, __uint_as_float((unsigned int)(e3 >> 32)));
        e0 = f0; e1 = f1; e2 = f2; e3 = f3;
        j += 4;
    }
    if (j + 4 <= end) {
        const uint4 v0 = __ldg(xw + (size_t)(unsigned int)(e0 & 0xffffffffu) * 32 + lane);
        const uint4 v1 = __ldg(xw + (size_t)(unsigned int)(e1 & 0xffffffffu) * 32 + lane);
        const uint4 v2 = __ldg(xw + (size_t)(unsigned int)(e2 & 0xffffffffu) * 32 + lane);
        const uint4 v3 = __ldg(xw + (size_t)(unsigned int)(e3 & 0xffffffffu) * 32 + lane);
        fma_u4(A, v0, __uint_as_float((unsigned int)(e0 >> 32)));
        fma_u4(A, v1, __uint_as_float((unsigned int)(e1 >> 32)));
        fma_u4(A, v2, __uint_as_float((unsigned int)(e2 >> 32)));
        fma_u4(A, v3, __uint_as_float((unsigned int)(e3 >> 32)));
        j += 4;
    }
    {
        const int rem = end - j;
        if (rem > 0) {
            const unsigned long long t0 = __ldg(g_edge + j);
            const unsigned long long t1 = (rem > 1) ? __ldg(g_edge + j + 1) : 0;
            const unsigned long long t2 = (rem > 2) ? __ldg(g_edge + j + 2) : 0;
            const uint4 v0 = __ldg(xw + (size_t)(unsigned int)(t0 & 0xffffffffu) * 32 + lane);
            fma_u4(A, v0, __uint_as_float((unsigned int)(t0 >> 32)));
            if (rem > 1) {
                const uint4 v1 = __ldg(xw + (size_t)(unsigned int)(t1 & 0xffffffffu) * 32 + lane);
                fma_u4(A, v1, __uint_as_float((unsigned int)(t1 >> 32)));
            }
            if (rem > 2) {
                const uint4 v2 = __ldg(xw + (size_t)(unsigned int)(t2 & 0xffffffffu) * 32 + lane);
                fma_u4(A, v2, __uint_as_float((unsigned int)(t2 >> 32)));
            }
        }
    }

    // epilogue: +bias, tanh
    const float4 bv0 = __ldg((const float4*)bias + (lane & 7) * 2);
    const float4 bv1 = __ldg((const float4*)bias + (lane & 7) * 2 + 1);
    float o[8];
    o[0] = tanhf(A[0] + bv0.x); o[1] = tanhf(A[1] + bv0.y);
    o[2] = tanhf(A[2] + bv0.z); o[3] = tanhf(A[3] + bv0.w);
    o[4] = tanhf(A[4] + bv1.x); o[5] = tanhf(A[5] + bv1.y);
    o[6] = tanhf(A[6] + bv1.z); o[7] = tanhf(A[7] + bv1.w);

    if (FINAL) {
        // fp32 (B,N,D): lane covers b = lane/8, d = (lane%8)*8 .. +7
        const int b = lane >> 3;
        float4* o4 = (float4*)dst + ((size_t)b * NN + node) * 16 + (lane & 7) * 2;
        o4[0] = make_float4(o[0], o[1], o[2], o[3]);
        o4[1] = make_float4(o[4], o[5], o[6], o[7]);
    } else {
        const __half2 p0 = __floats2half2_rn(o[0], o[1]);
        const __half2 p1 = __floats2half2_rn(o[2], o[3]);
        const __half2 p2 = __floats2half2_rn(o[4], o[5]);
        const __half2 p3 = __floats2half2_rn(o[6], o[7]);
        uint4 u;
        u.x = *(const unsigned int*)&p0;
        u.y = *(const unsigned int*)&p1;
        u.z = *(const unsigned int*)&p2;
        u.w = *(const unsigned int*)&p3;
        g_h1h[(size_t)node * 32 + lane] = u;
    }
}

// ---------------------------------------------------------------------------
extern "C" void kernel_launch(void* const* d_in, const int* in_sizes, int n_in,
                              void* d_out, int out_size) {
    const float* h  = (const float*)d_in[1];
    const int*   ei = (const int*)d_in[2];
    const float* W1 = (const float*)d_in[3];
    const float* b1 = (const float*)d_in[4];
    const float* W2 = (const float*)d_in[5];
    const float* b2 = (const float*)d_in[6];
    float* out = (float*)d_out;

    const int E  = in_sizes[2] / 2;
    const int eB = (E + 255) / 256;
    const int cB = (E / 4 + 255) / 256 + 1;
    const int aB = (NN + 7) / 8;

    count_k<<<cB, 256>>>(ei, E);            // 1
    scan_k <<<SCAN_B, 256>>>(E);            // 2
    fill_k <<<eB, 256>>>(ei, E);            // 3
    gemm1_k<<<GEMM_B, 256>>>(h, W1);        // 4  <- profiled
    agg_k<false><<<aB, 256>>>(b1, nullptr); // 5
    gemm2_k<<<GEMM_B, 256>>>(W2);           // 6
    agg_k<true> <<<aB, 256>>>(b2, out);     // 7
}

// round 7
// speedup vs baseline: 3.4865x; 1.3837x over previous
#include <cuda_runtime.h>
#include <cuda_fp16.h>
#include <math.h>

// Fixed-shape problem: B=4, N=50000, E=800000, D=64
#define NN 50000
#define BB 4
#define DD 64
#define NR (NN * BB)          // 200000 rows (node-major: row = node*4 + b)
#define SCAN_B 196            // ceil(50000/256)
#define GEMM_B ((NR + 127) / 128)   // 1563 blocks (last tile 64 rows)
#define FLAG_BIT 0x40000000

// Scratch (__device__ globals per allocation-free rule)
__device__ uint4  g_xwh[(size_t)NR * 8];        // linear output, fp16, 25.6 MB
__device__ uint4  g_h1h[(size_t)NR * 8];        // layer-1 activation, fp16, 25.6 MB
__device__ float  g_dis[NN];                    // rsqrt(deg+1)
__device__ int    g_deg[NN];                    // zero-init; re-zeroed each pass
__device__ int    g_off[NN + 1];                // CSR offsets (by target node)
__device__ int    g_cur[NN];                    // fill cursors
__device__ unsigned long long g_edge[800000];   // packed (src, nrm fp32)
__device__ int    g_pub[SCAN_B];                // lookback publications

// ---------------------------------------------------------------------------
__global__ __launch_bounds__(256) void count_k(const int* __restrict__ ei, int E) {
    const int t = blockIdx.x * blockDim.x + threadIdx.x;
    if (blockIdx.x == 0 && threadIdx.x < SCAN_B) g_pub[threadIdx.x] = 0;
    const int e4 = t * 4;
    if (e4 + 4 <= E) {
        const int4 c = __ldg((const int4*)(ei + E) + t);
        atomicAdd(&g_deg[c.x], 1);
        atomicAdd(&g_deg[c.y], 1);
        atomicAdd(&g_deg[c.z], 1);
        atomicAdd(&g_deg[c.w], 1);
    } else {
        for (int e = e4; e < E; e++) atomicAdd(&g_deg[ei[E + e]], 1);
    }
}

// single-pass exclusive scan (decoupled lookback); emits g_dis, re-zeroes g_deg
__global__ __launch_bounds__(256) void scan_k(int E) {
    __shared__ int sh[256];
    __shared__ int s_prefix;
    const int tid = threadIdx.x;
    const int b   = blockIdx.x;
    const int idx = b * 256 + tid;

    int v = 0;
    if (idx < NN) {
        v = g_deg[idx];
        g_deg[idx] = 0;
        g_dis[idx] = rsqrtf((float)(v + 1));
    }
    sh[tid] = v;
    __syncthreads();
#pragma unroll
    for (int o = 1; o < 256; o <<= 1) {
        int t2 = (tid >= o) ? sh[tid - o] : 0;
        __syncthreads();
        sh[tid] += t2;
        __syncthreads();
    }
    const int incl = sh[tid];
    const int total = sh[255];

    if (tid == 0) {
        s_prefix = 0;
        __threadfence();
        atomicExch(&g_pub[b], total | FLAG_BIT);
        if (b == 0) g_off[NN] = E;
    }
    __syncthreads();

    if (tid < b) {
        int p;
        do { p = atomicAdd(&g_pub[tid], 0); } while (!(p & FLAG_BIT));
        atomicAdd(&s_prefix, p & ~FLAG_BIT);
    }
    __syncthreads();

    if (idx < NN) {
        const int off = s_prefix + incl - v;
        g_off[idx] = off;
        g_cur[idx] = off;
    }
}

__global__ __launch_bounds__(256) void fill_k(const int* __restrict__ ei, int E) {
    const int t = blockIdx.x * 256 + threadIdx.x;
    const int e4 = t * 4;
    if (e4 + 4 <= E) {
        const int4 r = __ldg((const int4*)ei + t);
        const int4 c = __ldg((const int4*)(ei + E) + t);
        int p0 = atomicAdd(&g_cur[c.x], 1);
        int p1 = atomicAdd(&g_cur[c.y], 1);
        int p2 = atomicAdd(&g_cur[c.z], 1);
        int p3 = atomicAdd(&g_cur[c.w], 1);
        g_edge[p0] = (unsigned long long)(unsigned int)r.x |
                     ((unsigned long long)__float_as_uint(g_dis[r.x] * g_dis[c.x]) << 32);
        g_edge[p1] = (unsigned long long)(unsigned int)r.y |
                     ((unsigned long long)__float_as_uint(g_dis[r.y] * g_dis[c.y]) << 32);
        g_edge[p2] = (unsigned long long)(unsigned int)r.z |
                     ((unsigned long long)__float_as_uint(g_dis[r.z] * g_dis[c.z]) << 32);
        g_edge[p3] = (unsigned long long)(unsigned int)r.w |
                     ((unsigned long long)__float_as_uint(g_dis[r.w] * g_dis[c.w]) << 32);
    } else {
        for (int e = e4; e < E; e++) {
            const int r = ei[e], c = ei[E + e];
            const int pos = atomicAdd(&g_cur[c], 1);
            g_edge[pos] = (unsigned long long)(unsigned int)r |
                          ((unsigned long long)__float_as_uint(g_dis[r] * g_dis[c]) << 32);
        }
    }
}

// ---------------------------------------------------------------------------
// GEMM: 128 rows x 64 cols per 256-thread block, 4x8 register tile,
// float4 A-fragment loads (12 LDS.128 per 128 FMA).
// MODE 0: x fp32 (B,N,D). MODE 1: x = g_h1h fp16. Output: g_xwh fp16.
// ---------------------------------------------------------------------------
template <int MODE>
__device__ __forceinline__ void gemm_body(const float* __restrict__ x,
                                          const float* __restrict__ W,
                                          int blk) {
    __shared__ __align__(16) float Ws[64 * 68];    // 17.4 KB
    __shared__ __align__(16) float xs[128 * 68];   // 34.8 KB
    const int tid = threadIdx.x;

    // W: 1024 float4, 4 per thread
    {
        const float4* W4 = (const float4*)W;
#pragma unroll
        for (int i = 0; i < 4; i++) {
            const int q = i * 256 + tid;
            const int row = q >> 4, c4 = q & 15;
            *(float4*)&Ws[row * 68 + c4 * 4] = __ldg(W4 + q);
        }
    }

    const int base = blk * 128;
    if (MODE == 0) {
        // 128 rows x 16 float4 = 2048, 8 per thread
#pragma unroll
        for (int i = 0; i < 8; i++) {
            const int q = i * 256 + tid;
            const int row = q >> 4, c4 = q & 15;
            int rr = base + row; if (rr >= NR) rr = NR - 1;
            const int n = rr >> 2, bb = rr & 3;
            const float4 v = __ldg((const float4*)(x + ((size_t)bb * NN + n) * DD) + c4);
            *(float4*)&xs[row * 68 + c4 * 4] = v;
        }
    } else {
        // 128 rows x 8 uint4 = 1024, 4 per thread
#pragma unroll
        for (int i = 0; i < 4; i++) {
            const int q = i * 256 + tid;
            const int row = q >> 3, u4 = q & 7;
            int rr = base + row; if (rr >= NR) rr = NR - 1;
            const uint4 u = __ldg(&g_h1h[(size_t)rr * 8 + u4]);
            const __half2* hp = (const __half2*)&u;
            const float2 f0 = __half22float2(hp[0]);
            const float2 f1 = __half22float2(hp[1]);
            const float2 f2 = __half22float2(hp[2]);
            const float2 f3 = __half22float2(hp[3]);
            float* xp = &xs[row * 68 + u4 * 8];
            *(float4*)xp       = make_float4(f0.x, f0.y, f1.x, f1.y);
            *(float4*)(xp + 4) = make_float4(f2.x, f2.y, f3.x, f3.y);
        }
    }
    __syncthreads();

    const int r4 = (tid >> 3) * 4;   // 0..124
    const int c8 = (tid & 7) * 8;    // 0..56
    float acc[4][8];
#pragma unroll
    for (int i = 0; i < 4; i++)
#pragma unroll
        for (int j = 0; j < 8; j++) acc[i][j] = 0.0f;

#pragma unroll
    for (int k4 = 0; k4 < 64; k4 += 4) {
        float4 a[4];
#pragma unroll
        for (int i = 0; i < 4; i++)
            a[i] = *(const float4*)&xs[(r4 + i) * 68 + k4];
#pragma unroll
        for (int kk = 0; kk < 4; kk++) {
            const float4 w0 = *(const float4*)&Ws[(k4 + kk) * 68 + c8];
            const float4 w1 = *(const float4*)&Ws[(k4 + kk) * 68 + c8 + 4];
#pragma unroll
            for (int i = 0; i < 4; i++) {
                const float av = (kk == 0) ? a[i].x : (kk == 1) ? a[i].y
                               : (kk == 2) ? a[i].z : a[i].w;
                acc[i][0] = fmaf(av, w0.x, acc[i][0]);
                acc[i][1] = fmaf(av, w0.y, acc[i][1]);
                acc[i][2] = fmaf(av, w0.z, acc[i][2]);
                acc[i][3] = fmaf(av, w0.w, acc[i][3]);
                acc[i][4] = fmaf(av, w1.x, acc[i][4]);
                acc[i][5] = fmaf(av, w1.y, acc[i][5]);
                acc[i][6] = fmaf(av, w1.z, acc[i][6]);
                acc[i][7] = fmaf(av, w1.w, acc[i][7]);
            }
        }
    }

#pragma unroll
    for (int i = 0; i < 4; i++) {
        const int rr = base + r4 + i;
        if (rr < NR) {
            const __half2 p0 = __floats2half2_rn(acc[i][0], acc[i][1]);
            const __half2 p1 = __floats2half2_rn(acc[i][2], acc[i][3]);
            const __half2 p2 = __floats2half2_rn(acc[i][4], acc[i][5]);
            const __half2 p3 = __floats2half2_rn(acc[i][6], acc[i][7]);
            uint4 u;
            u.x = *(const unsigned int*)&p0;
            u.y = *(const unsigned int*)&p1;
            u.z = *(const unsigned int*)&p2;
            u.w = *(const unsigned int*)&p3;
            g_xwh[(size_t)rr * 8 + (tid & 7)] = u;
        }
    }
}

__global__ __launch_bounds__(256) void gemm1_k(const float* __restrict__ x,
                                               const float* __restrict__ W) {
    gemm_body<0>(x, W, blockIdx.x);
}
__global__ __launch_bounds__(256) void gemm2_k(const float* __restrict__ W) {
    gemm_body<1>(nullptr, W, blockIdx.x);
}

// ---------------------------------------------------------------------------
// Aggregation: warp per node; lane owns uint4 slice `lane` (8 halfs).
// ---------------------------------------------------------------------------
__device__ __forceinline__ void fma_u4(float* A, const uint4 u, const float nm) {
    const __half2* hp = (const __half2*)&u;
    const float2 f0 = __half22float2(hp[0]);
    const float2 f1 = __half22float2(hp[1]);
    const float2 f2 = __half22float2(hp[2]);
    const float2 f3 = __half22float2(hp[3]);
    A[0] = fmaf(f0.x, nm, A[0]); A[1] = fmaf(f0.y, nm, A[1]);
    A[2] = fmaf(f1.x, nm, A[2]); A[3] = fmaf(f1.y, nm, A[3]);
    A[4] = fmaf(f2.x, nm, A[4]); A[5] = fmaf(f2.y, nm, A[5]);
    A[6] = fmaf(f3.x, nm, A[6]); A[7] = fmaf(f3.y, nm, A[7]);
}

template <bool FINAL>
__global__ __launch_bounds__(256) void agg_k(const float* __restrict__ bias,
                                             float* __restrict__ dst) {
    const int node = blockIdx.x * 8 + (threadIdx.x >> 5);
    const int lane = threadIdx.x & 31;
    if (node >= NN) return;

    const uint4* __restrict__ xw = g_xwh;
    float A[8];

    {
        const float dn = g_dis[node];
        const float sl = dn * dn;
        const uint4 u = __ldg(xw + (size_t)node * 32 + lane);
        const __half2* hp = (const __half2*)&u;
        const float2 f0 = __half22float2(hp[0]);
        const float2 f1 = __half22float2(hp[1]);
        const float2 f2 = __half22float2(hp[2]);
        const float2 f3 = __half22float2(hp[3]);
        A[0] = f0.x * sl; A[1] = f0.y * sl;
        A[2] = f1.x * sl; A[3] = f1.y * sl;
        A[4] = f2.x * sl; A[5] = f2.y * sl;
        A[6] = f3.x * sl; A[7] = f3.y * sl;
    }

    int j = g_off[node];
    const int end = g_off[node + 1];

    unsigned long long e0 = 0, e1 = 0, e2 = 0, e3 = 0;
    if (j + 4 <= end) {
        e0 = __ldg(g_edge + j);
        e1 = __ldg(g_edge + j + 1);
        e2 = __ldg(g_edge + j + 2);
        e3 = __ldg(g_edge + j + 3);
    }
    while (j + 8 <= end) {
        const unsigned long long f0 = __ldg(g_edge + j + 4);
        const unsigned long long f1 = __ldg(g_edge + j + 5);
        const unsigned long long f2 = __ldg(g_edge + j + 6);
        const unsigned long long f3 = __ldg(g_edge + j + 7);
        const uint4 v0 = __ldg(xw + (size_t)(unsigned int)(e0 & 0xffffffffu) * 32 + lane);
        const uint4 v1 = __ldg(xw + (size_t)(unsigned int)(e1 & 0xffffffffu) * 32 + lane);
        const uint4 v2 = __ldg(xw + (size_t)(unsigned int)(e2 & 0xffffffffu) * 32 + lane);
        const uint4 v3 = __ldg(xw + (size_t)(unsigned int)(e3 & 0xffffffffu) * 32 + lane);
        fma_u4(A, v0, __uint_as_float((unsigned int)(e0 >> 32)));
        fma_u4(A, v1, __uint_as_float((unsigned int)(e1 >> 32)));
        fma_u4(A, v2, __uint_as_float((unsigned int)(e2 >> 32)));
        fma_u4(A, v3, __uint_as_float((unsigned int)(e3 >> 32)));
        e0 = f0; e1 = f1; e2 = f2; e3 = f3;
        j += 4;
    }
    if (j + 4 <= end) {
        const uint4 v0 = __ldg(xw + (size_t)(unsigned int)(e0 & 0xffffffffu) * 32 + lane);
        const uint4 v1 = __ldg(xw + (size_t)(unsigned int)(e1 & 0xffffffffu) * 32 + lane);
        const uint4 v2 = __ldg(xw + (size_t)(unsigned int)(e2 & 0xffffffffu) * 32 + lane);
        const uint4 v3 = __ldg(xw + (size_t)(unsigned int)(e3 & 0xffffffffu) * 32 + lane);
        fma_u4(A, v0, __uint_as_float((unsigned int)(e0 >> 32)));
        fma_u4(A, v1, __uint_as_float((unsigned int)(e1 >> 32)));
        fma_u4(A, v2, __uint_as_float((unsigned int)(e2 >> 32)));
        fma_u4(A, v3, __uint_as_float((unsigned int)(e3 >> 32)));
        j += 4;
    }
    {
        const int rem = end - j;
        if (rem > 0) {
            const unsigned long long t0 = __ldg(g_edge + j);
            const unsigned long long t1 = (rem > 1) ? __ldg(g_edge + j + 1) : 0;
            const unsigned long long t2 = (rem > 2) ? __ldg(g_edge + j + 2) : 0;
            const uint4 v0 = __ldg(xw + (size_t)(unsigned int)(t0 & 0xffffffffu) * 32 + lane);
            fma_u4(A, v0, __uint_as_float((unsigned int)(t0 >> 32)));
            if (rem > 1) {
                const uint4 v1 = __ldg(xw + (size_t)(unsigned int)(t1 & 0xffffffffu) * 32 + lane);
                fma_u4(A, v1, __uint_as_float((unsigned int)(t1 >> 32)));
            }
            if (rem > 2) {
                const uint4 v2 = __ldg(xw + (size_t)(unsigned int)(t2 & 0xffffffffu) * 32 + lane);
                fma_u4(A, v2, __uint_as_float((unsigned int)(t2 >> 32)));
            }
        }
    }

    const float4 bv0 = __ldg((const float4*)bias + (lane & 7) * 2);
    const float4 bv1 = __ldg((const float4*)bias + (lane & 7) * 2 + 1);
    float o[8];
    o[0] = tanhf(A[0] + bv0.x); o[1] = tanhf(A[1] + bv0.y);
    o[2] = tanhf(A[2] + bv0.z); o[3] = tanhf(A[3] + bv0.w);
    o[4] = tanhf(A[4] + bv1.x); o[5] = tanhf(A[5] + bv1.y);
    o[6] = tanhf(A[6] + bv1.z); o[7] = tanhf(A[7] + bv1.w);

    if (FINAL) {
        const int b = lane >> 3;
        float4* o4 = (float4*)dst + ((size_t)b * NN + node) * 16 + (lane & 7) * 2;
        o4[0] = make_float4(o[0], o[1], o[2], o[3]);
        o4[1] = make_float4(o[4], o[5], o[6], o[7]);
    } else {
        const __half2 p0 = __floats2half2_rn(o[0], o[1]);
        const __half2 p1 = __floats2half2_rn(o[2], o[3]);
        const __half2 p2 = __floats2half2_rn(o[4], o[5]);
        const __half2 p3 = __floats2half2_rn(o[6], o[7]);
        uint4 u;
        u.x = *(const unsigned int*)&p0;
        u.y = *(const unsigned int*)&p1;
        u.z = *(const unsigned int*)&p2;
        u.w = *(const unsigned int*)&p3;
        g_h1h[(size_t)node * 32 + lane] = u;
    }
}

// ---------------------------------------------------------------------------
extern "C" void kernel_launch(void* const* d_in, const int* in_sizes, int n_in,
                              void* d_out, int out_size) {
    const float* h  = (const float*)d_in[1];
    const int*   ei = (const int*)d_in[2];
    const float* W1 = (const float*)d_in[3];
    const float* b1 = (const float*)d_in[4];
    const float* W2 = (const float*)d_in[5];
    const float* b2 = (const float*)d_in[6];
    float* out = (float*)d_out;

    const int E  = in_sizes[2] / 2;
    const int cB = (E / 4 + 255) / 256 + 1;
    const int aB = (NN + 7) / 8;

    count_k<<<cB, 256>>>(ei, E);            // 1
    scan_k <<<SCAN_B, 256>>>(E);            // 2
    fill_k <<<cB, 256>>>(ei, E);            // 3
    gemm1_k<<<GEMM_B, 256>>>(h, W1);        // 4  <- profiled
    agg_k<false><<<aB, 256>>>(b1, nullptr); // 5
    gemm2_k<<<GEMM_B, 256>>>(W2);           // 6
    agg_k<true> <<<aB, 256>>>(b2, out);     // 7
}

// round 8
// speedup vs baseline: 5.5664x; 1.5966x over previous
#include <cuda_runtime.h>
#include <cuda_fp16.h>
#include <math.h>

// Fixed-shape problem: B=4, N=50000, E=800000, D=64
#define NN 50000
#define BB 4
#define DD 64
#define NR (NN * BB)                 // 200000 rows (node-major: row = node*4 + b)
#define SCAN_B 196                   // ceil(50000/256)
#define GEMM_B ((NR + 127) / 128)    // 1563 blocks
#define FLAG_BIT 0x40000000
#define AP 72                        // padded smem row stride (halfs) = 144 B

// Scratch (__device__ globals per allocation-free rule)
__device__ uint4  g_xwh[(size_t)NR * 8];        // linear output, fp16, 25.6 MB
__device__ uint4  g_h1h[(size_t)NR * 8];        // layer-1 activation, fp16, 25.6 MB
__device__ float  g_dis[NN];                    // rsqrt(deg+1)
__device__ int    g_deg[NN];                    // zero-init; re-zeroed each pass
__device__ int    g_off[NN + 1];                // CSR offsets (by target node)
__device__ int    g_cur[NN];                    // fill cursors
__device__ unsigned long long g_edge[800000];   // packed (src, nrm fp32)
__device__ int    g_pub[SCAN_B];                // lookback publications

static __device__ __forceinline__ unsigned smem_u32(const void* p) {
    return (unsigned)__cvta_generic_to_shared(p);
}

// ---------------------------------------------------------------------------
__global__ __launch_bounds__(256) void count_k(const int* __restrict__ ei, int E) {
    const int t = blockIdx.x * blockDim.x + threadIdx.x;
    if (blockIdx.x == 0 && threadIdx.x < SCAN_B) g_pub[threadIdx.x] = 0;
    const int e4 = t * 4;
    if (e4 + 4 <= E) {
        const int4 c = __ldg((const int4*)(ei + E) + t);
        atomicAdd(&g_deg[c.x], 1);
        atomicAdd(&g_deg[c.y], 1);
        atomicAdd(&g_deg[c.z], 1);
        atomicAdd(&g_deg[c.w], 1);
    } else {
        for (int e = e4; e < E; e++) atomicAdd(&g_deg[ei[E + e]], 1);
    }
}

__global__ __launch_bounds__(256) void scan_k(int E) {
    __shared__ int sh[256];
    __shared__ int s_prefix;
    const int tid = threadIdx.x;
    const int b   = blockIdx.x;
    const int idx = b * 256 + tid;

    int v = 0;
    if (idx < NN) {
        v = g_deg[idx];
        g_deg[idx] = 0;
        g_dis[idx] = rsqrtf((float)(v + 1));
    }
    sh[tid] = v;
    __syncthreads();
#pragma unroll
    for (int o = 1; o < 256; o <<= 1) {
        int t2 = (tid >= o) ? sh[tid - o] : 0;
        __syncthreads();
        sh[tid] += t2;
        __syncthreads();
    }
    const int incl = sh[tid];
    const int total = sh[255];

    if (tid == 0) {
        s_prefix = 0;
        __threadfence();
        atomicExch(&g_pub[b], total | FLAG_BIT);
        if (b == 0) g_off[NN] = E;
    }
    __syncthreads();

    if (tid < b) {
        int p;
        do { p = atomicAdd(&g_pub[tid], 0); } while (!(p & FLAG_BIT));
        atomicAdd(&s_prefix, p & ~FLAG_BIT);
    }
    __syncthreads();

    if (idx < NN) {
        const int off = s_prefix + incl - v;
        g_off[idx] = off;
        g_cur[idx] = off;
    }
}

__global__ __launch_bounds__(256) void fill_k(const int* __restrict__ ei, int E) {
    const int t = blockIdx.x * 256 + threadIdx.x;
    const int e4 = t * 4;
    if (e4 + 4 <= E) {
        const int4 r = __ldg((const int4*)ei + t);
        const int4 c = __ldg((const int4*)(ei + E) + t);
        int p0 = atomicAdd(&g_cur[c.x], 1);
        int p1 = atomicAdd(&g_cur[c.y], 1);
        int p2 = atomicAdd(&g_cur[c.z], 1);
        int p3 = atomicAdd(&g_cur[c.w], 1);
        g_edge[p0] = (unsigned long long)(unsigned int)r.x |
                     ((unsigned long long)__float_as_uint(g_dis[r.x] * g_dis[c.x]) << 32);
        g_edge[p1] = (unsigned long long)(unsigned int)r.y |
                     ((unsigned long long)__float_as_uint(g_dis[r.y] * g_dis[c.y]) << 32);
        g_edge[p2] = (unsigned long long)(unsigned int)r.z |
                     ((unsigned long long)__float_as_uint(g_dis[r.z] * g_dis[c.z]) << 32);
        g_edge[p3] = (unsigned long long)(unsigned int)r.w |
                     ((unsigned long long)__float_as_uint(g_dis[r.w] * g_dis[c.w]) << 32);
    } else {
        for (int e = e4; e < E; e++) {
            const int r = ei[e], c = ei[E + e];
            const int pos = atomicAdd(&g_cur[c], 1);
            g_edge[pos] = (unsigned long long)(unsigned int)r |
                          ((unsigned long long)__float_as_uint(g_dis[r] * g_dis[c]) << 32);
        }
    }
}

// ---------------------------------------------------------------------------
// Tensor-core GEMM: 128 rows x 64 cols per 256-thread block (8 warps,
// 16 rows/warp), mma.sync m16n8k16 fp16 in / fp32 accum.
// MODE 0: x fp32 (B,N,D). MODE 1: x = g_h1h fp16. Output: g_xwh fp16.
// ---------------------------------------------------------------------------
template <int MODE>
__device__ __forceinline__ void gemm_body(const float* __restrict__ x,
                                          const float* __restrict__ W,
                                          int blk) {
    __shared__ __align__(16) __half As[128 * AP];   // 18.4 KB
    __shared__ __align__(16) __half Wsh[64 * AP];   // 9.2 KB
    const int tid  = threadIdx.x;
    const int warp = tid >> 5;
    const int lane = tid & 31;

    // W: 4096 fp32 -> fp16 smem (4 float4 per thread)
    {
        const float4* W4 = (const float4*)W;
#pragma unroll
        for (int i = 0; i < 4; i++) {
            const int q = i * 256 + tid;          // 0..1023
            const int row = q >> 4, c4 = q & 15;
            const float4 v = __ldg(W4 + q);
            *(__half2*)&Wsh[row * AP + c4 * 4]     = __floats2half2_rn(v.x, v.y);
            *(__half2*)&Wsh[row * AP + c4 * 4 + 2] = __floats2half2_rn(v.z, v.w);
        }
    }

    const int base = blk * 128;
    if (MODE == 0) {
#pragma unroll
        for (int i = 0; i < 8; i++) {
            const int q = i * 256 + tid;          // 0..2047
            const int row = q >> 4, c4 = q & 15;
            int rr = base + row; if (rr >= NR) rr = NR - 1;
            const int n = rr >> 2, bb = rr & 3;
            const float4 v = __ldg((const float4*)(x + ((size_t)bb * NN + n) * DD) + c4);
            *(__half2*)&As[row * AP + c4 * 4]     = __floats2half2_rn(v.x, v.y);
            *(__half2*)&As[row * AP + c4 * 4 + 2] = __floats2half2_rn(v.z, v.w);
        }
    } else {
#pragma unroll
        for (int i = 0; i < 4; i++) {
            const int q = i * 256 + tid;          // 0..1023
            const int row = q >> 3, u4 = q & 7;
            int rr = base + row; if (rr >= NR) rr = NR - 1;
            const uint4 u = __ldg(&g_h1h[(size_t)rr * 8 + u4]);
            *(uint4*)&As[row * AP + u4 * 8] = u;
        }
    }
    __syncthreads();

    float acc[8][4];   // [n-tile][mma reg]
#pragma unroll
    for (int t = 0; t < 8; t++)
#pragma unroll
        for (int r = 0; r < 4; r++) acc[t][r] = 0.0f;

#pragma unroll
    for (int k0 = 0; k0 < 64; k0 += 16) {
        // A fragment (16x16): lanes 0-15 -> rows, k0; lanes 16-31 -> rows, k0+8
        unsigned a0, a1, a2, a3;
        {
            const int arow = warp * 16 + (lane & 15);
            const int acol = k0 + ((lane >> 4) << 3);
            const unsigned addrA = smem_u32(&As[arow * AP + acol]);
            asm volatile(
                "ldmatrix.sync.aligned.m8n8.x4.shared.b16 {%0,%1,%2,%3}, [%4];"
                : "=r"(a0), "=r"(a1), "=r"(a2), "=r"(a3) : "r"(addrA));
        }
#pragma unroll
        for (int nt = 0; nt < 8; nt += 2) {
            // B fragments for n-tiles nt, nt+1 (16x8 each), via x4 trans:
            // m0=(k0..k0+7, nt), m1=(k0+8.., nt), m2=(k0.., nt+1), m3=(k0+8.., nt+1)
            unsigned b0, b1, b2, b3;
            {
                const int l8  = lane & 7;
                const int sel = lane >> 3;                   // 0..3
                const int brow = k0 + l8 + ((sel & 1) << 3);
                const int bcol = (nt + (sel >> 1)) * 8;
                const unsigned addrB = smem_u32(&Wsh[brow * AP + bcol]);
                asm volatile(
                    "ldmatrix.sync.aligned.m8n8.x4.trans.shared.b16 {%0,%1,%2,%3}, [%4];"
                    : "=r"(b0), "=r"(b1), "=r"(b2), "=r"(b3) : "r"(addrB));
            }
            asm volatile(
                "mma.sync.aligned.m16n8k16.row.col.f32.f16.f16.f32 "
                "{%0,%1,%2,%3}, {%4,%5,%6,%7}, {%8,%9}, {%0,%1,%2,%3};"
                : "+f"(acc[nt][0]), "+f"(acc[nt][1]), "+f"(acc[nt][2]), "+f"(acc[nt][3])
                : "r"(a0), "r"(a1), "r"(a2), "r"(a3), "r"(b0), "r"(b1));
            asm volatile(
                "mma.sync.aligned.m16n8k16.row.col.f32.f16.f16.f32 "
                "{%0,%1,%2,%3}, {%4,%5,%6,%7}, {%8,%9}, {%0,%1,%2,%3};"
                : "+f"(acc[nt + 1][0]), "+f"(acc[nt + 1][1]), "+f"(acc[nt + 1][2]), "+f"(acc[nt + 1][3])
                : "r"(a0), "r"(a1), "r"(a2), "r"(a3), "r"(b2), "r"(b3));
        }
    }

    // store: lane (g=lane>>2, tig=lane&3) holds rows g and g+8 of the warp tile,
    // cols nt*8 + tig*2 (+1). fp16 half2 stores.
    {
        __half* xwp = (__half*)g_xwh;
        const int g   = lane >> 2;
        const int tig = lane & 3;
        const int row_lo = base + warp * 16 + g;
        const int row_hi = row_lo + 8;
        if (row_lo < NR) {
            __half* p = xwp + (size_t)row_lo * 64 + tig * 2;
#pragma unroll
            for (int nt = 0; nt < 8; nt++)
                *(__half2*)(p + nt * 8) = __floats2half2_rn(acc[nt][0], acc[nt][1]);
        }
        if (row_hi < NR) {
            __half* p = xwp + (size_t)row_hi * 64 + tig * 2;
#pragma unroll
            for (int nt = 0; nt < 8; nt++)
                *(__half2*)(p + nt * 8) = __floats2half2_rn(acc[nt][2], acc[nt][3]);
        }
    }
}

__global__ __launch_bounds__(256) void gemm1_k(const float* __restrict__ x,
                                               const float* __restrict__ W) {
    gemm_body<0>(x, W, blockIdx.x);
}
__global__ __launch_bounds__(256) void gemm2_k(const float* __restrict__ W) {
    gemm_body<1>(nullptr, W, blockIdx.x);
}

// ---------------------------------------------------------------------------
// Aggregation: warp per node; lane owns uint4 slice `lane` (8 halfs).
// ---------------------------------------------------------------------------
__device__ __forceinline__ void fma_u4(float* A, const uint4 u, const float nm) {
    const __half2* hp = (const __half2*)&u;
    const float2 f0 = __half22float2(hp[0]);
    const float2 f1 = __half22float2(hp[1]);
    const float2 f2 = __half22float2(hp[2]);
    const float2 f3 = __half22float2(hp[3]);
    A[0] = fmaf(f0.x, nm, A[0]); A[1] = fmaf(f0.y, nm, A[1]);
    A[2] = fmaf(f1.x, nm, A[2]); A[3] = fmaf(f1.y, nm, A[3]);
    A[4] = fmaf(f2.x, nm, A[4]); A[5] = fmaf(f2.y, nm, A[5]);
    A[6] = fmaf(f3.x, nm, A[6]); A[7] = fmaf(f3.y, nm, A[7]);
}

template <bool FINAL>
__global__ __launch_bounds__(256) void agg_k(const float* __restrict__ bias,
                                             float* __restrict__ dst) {
    const int node = blockIdx.x * 8 + (threadIdx.x >> 5);
    const int lane = threadIdx.x & 31;
    if (node >= NN) return;

    const uint4* __restrict__ xw = g_xwh;
    float A[8];

    {
        const float dn = g_dis[node];
        const float sl = dn * dn;
        const uint4 u = __ldg(xw + (size_t)node * 32 + lane);
        const __half2* hp = (const __half2*)&u;
        const float2 f0 = __half22float2(hp[0]);
        const float2 f1 = __half22float2(hp[1]);
        const float2 f2 = __half22float2(hp[2]);
        const float2 f3 = __half22float2(hp[3]);
        A[0] = f0.x * sl; A[1] = f0.y * sl;
        A[2] = f1.x * sl; A[3] = f1.y * sl;
        A[4] = f2.x * sl; A[5] = f2.y * sl;
        A[6] = f3.x * sl; A[7] = f3.y * sl;
    }

    int j = g_off[node];
    const int end = g_off[node + 1];

    unsigned long long e0 = 0, e1 = 0, e2 = 0, e3 = 0;
    if (j + 4 <= end) {
        e0 = __ldg(g_edge + j);
        e1 = __ldg(g_edge + j + 1);
        e2 = __ldg(g_edge + j + 2);
        e3 = __ldg(g_edge + j + 3);
    }
    while (j + 8 <= end) {
        const unsigned long long f0 = __ldg(g_edge + j + 4);
        const unsigned long long f1 = __ldg(g_edge + j + 5);
        const unsigned long long f2 = __ldg(g_edge + j + 6);
        const unsigned long long f3 = __ldg(g_edge + j + 7);
        const uint4 v0 = __ldg(xw + (size_t)(unsigned int)(e0 & 0xffffffffu) * 32 + lane);
        const uint4 v1 = __ldg(xw + (size_t)(unsigned int)(e1 & 0xffffffffu) * 32 + lane);
        const uint4 v2 = __ldg(xw + (size_t)(unsigned int)(e2 & 0xffffffffu) * 32 + lane);
        const uint4 v3 = __ldg(xw + (size_t)(unsigned int)(e3 & 0xffffffffu) * 32 + lane);
        fma_u4(A, v0, __uint_as_float((unsigned int)(e0 >> 32)));
        fma_u4(A, v1, __uint_as_float((unsigned int)(e1 >> 32)));
        fma_u4(A, v2, __uint_as_float((unsigned int)(e2 >> 32)));
        fma_u4(A, v3, __uint_as_float((unsigned int)(e3 >> 32)));
        e0 = f0; e1 = f1; e2 = f2; e3 = f3;
        j += 4;
    }
    if (j + 4 <= end) {
        const uint4 v0 = __ldg(xw + (size_t)(unsigned int)(e0 & 0xffffffffu) * 32 + lane);
        const uint4 v1 = __ldg(xw + (size_t)(unsigned int)(e1 & 0xffffffffu) * 32 + lane);
        const uint4 v2 = __ldg(xw + (size_t)(unsigned int)(e2 & 0xffffffffu) * 32 + lane);
        const uint4 v3 = __ldg(xw + (size_t)(unsigned int)(e3 & 0xffffffffu) * 32 + lane);
        fma_u4(A, v0, __uint_as_float((unsigned int)(e0 >> 32)));
        fma_u4(A, v1, __uint_as_float((unsigned int)(e1 >> 32)));
        fma_u4(A, v2, __uint_as_float((unsigned int)(e2 >> 32)));
        fma_u4(A, v3, __uint_as_float((unsigned int)(e3 >> 32)));
        j += 4;
    }
    {
        const int rem = end - j;
        if (rem > 0) {
            const unsigned long long t0 = __ldg(g_edge + j);
            const unsigned long long t1 = (rem > 1) ? __ldg(g_edge + j + 1) : 0;
            const unsigned long long t2 = (rem > 2) ? __ldg(g_edge + j + 2) : 0;
            const uint4 v0 = __ldg(xw + (size_t)(unsigned int)(t0 & 0xffffffffu) * 32 + lane);
            fma_u4(A, v0, __uint_as_float((unsigned int)(t0 >> 32)));
            if (rem > 1) {
                const uint4 v1 = __ldg(xw + (size_t)(unsigned int)(t1 & 0xffffffffu) * 32 + lane);
                fma_u4(A, v1, __uint_as_float((unsigned int)(t1 >> 32)));
            }
            if (rem > 2) {
                const uint4 v2 = __ldg(xw + (size_t)(unsigned int)(t2 & 0xffffffffu) * 32 + lane);
                fma_u4(A, v2, __uint_as_float((unsigned int)(t2 >> 32)));
            }
        }
    }

    const float4 bv0 = __ldg((const float4*)bias + (lane & 7) * 2);
    const float4 bv1 = __ldg((const float4*)bias + (lane & 7) * 2 + 1);
    float o[8];
    o[0] = tanhf(A[0] + bv0.x); o[1] = tanhf(A[1] + bv0.y);
    o[2] = tanhf(A[2] + bv0.z); o[3] = tanhf(A[3] + bv0.w);
    o[4] = tanhf(A[4] + bv1.x); o[5] = tanhf(A[5] + bv1.y);
    o[6] = tanhf(A[6] + bv1.z); o[7] = tanhf(A[7] + bv1.w);

    if (FINAL) {
        const int b = lane >> 3;
        float4* o4 = (float4*)dst + ((size_t)b * NN + node) * 16 + (lane & 7) * 2;
        o4[0] = make_float4(o[0], o[1], o[2], o[3]);
        o4[1] = make_float4(o[4], o[5], o[6], o[7]);
    } else {
        const __half2 p0 = __floats2half2_rn(o[0], o[1]);
        const __half2 p1 = __floats2half2_rn(o[2], o[3]);
        const __half2 p2 = __floats2half2_rn(o[4], o[5]);
        const __half2 p3 = __floats2half2_rn(o[6], o[7]);
        uint4 u;
        u.x = *(const unsigned int*)&p0;
        u.y = *(const unsigned int*)&p1;
        u.z = *(const unsigned int*)&p2;
        u.w = *(const unsigned int*)&p3;
        g_h1h[(size_t)node * 32 + lane] = u;
    }
}

// ---------------------------------------------------------------------------
extern "C" void kernel_launch(void* const* d_in, const int* in_sizes, int n_in,
                              void* d_out, int out_size) {
    const float* h  = (const float*)d_in[1];
    const int*   ei = (const int*)d_in[2];
    const float* W1 = (const float*)d_in[3];
    const float* b1 = (const float*)d_in[4];
    const float* W2 = (const float*)d_in[5];
    const float* b2 = (const float*)d_in[6];
    float* out = (float*)d_out;

    const int E  = in_sizes[2] / 2;
    const int cB = (E / 4 + 255) / 256 + 1;
    const int aB = (NN + 7) / 8;

    count_k<<<cB, 256>>>(ei, E);            // 1
    scan_k <<<SCAN_B, 256>>>(E);            // 2
    fill_k <<<cB, 256>>>(ei, E);            // 3
    gemm1_k<<<GEMM_B, 256>>>(h, W1);        // 4  <- profiled
    agg_k<false><<<aB, 256>>>(b1, nullptr); // 5
    gemm2_k<<<GEMM_B, 256>>>(W2);           // 6
    agg_k<true> <<<aB, 256>>>(b2, out);     // 7
}

// round 9
// speedup vs baseline: 5.7938x; 1.0408x over previous
#include <cuda_runtime.h>
#include <cuda_fp16.h>
#include <math.h>

// Fixed-shape problem: B=4, N=50000, E=800000, D=64
#define NN 50000
#define BB 4
#define DD 64
#define NR (NN * BB)                 // 200000 rows (node-major: row = node*4 + b)
#define SCAN_B 196                   // ceil(50000/256)
#define GEMM_B ((NR + 127) / 128)    // 1563 blocks
#define FLAG_BIT 0x40000000
#define AP 72                        // padded smem row stride (halfs) = 144 B

// Scratch (__device__ globals per allocation-free rule)
__device__ uint4  g_xwh[(size_t)NR * 8];        // linear output, fp16, 25.6 MB
__device__ uint4  g_h1h[(size_t)NR * 8];        // layer-1 activation, fp16, 25.6 MB
__device__ float  g_dis[NN];                    // rsqrt(deg+1)
__device__ int    g_deg[NN];                    // zero-init; re-zeroed each pass
__device__ int    g_off[NN + 1];                // CSR offsets (by target node)
__device__ int    g_cur[NN];                    // fill cursors
__device__ unsigned long long g_edge[800000];   // packed (src, nrm fp32)
__device__ int    g_pub[SCAN_B];                // lookback publications

static __device__ __forceinline__ unsigned smem_u32(const void* p) {
    return (unsigned)__cvta_generic_to_shared(p);
}

// ---------------------------------------------------------------------------
// count body: degree histogram (4 edges/thread) + scan-flag reset
// ---------------------------------------------------------------------------
__device__ __forceinline__ void count_body(const int* __restrict__ ei, int E, int blk) {
    const int t = blk * 256 + threadIdx.x;
    if (blk == 0 && threadIdx.x < SCAN_B) g_pub[threadIdx.x] = 0;
    const int e4 = t * 4;
    if (e4 + 4 <= E) {
        const int4 c = __ldg((const int4*)(ei + E) + t);
        atomicAdd(&g_deg[c.x], 1);
        atomicAdd(&g_deg[c.y], 1);
        atomicAdd(&g_deg[c.z], 1);
        atomicAdd(&g_deg[c.w], 1);
    } else {
        for (int e = e4; e < E; e++) atomicAdd(&g_deg[ei[E + e]], 1);
    }
}

// ---------------------------------------------------------------------------
// single-pass exclusive scan (decoupled lookback); emits g_dis, re-zeroes g_deg
// ---------------------------------------------------------------------------
__global__ __launch_bounds__(256) void scan_k(int E) {
    __shared__ int sh[256];
    __shared__ int s_prefix;
    const int tid = threadIdx.x;
    const int b   = blockIdx.x;
    const int idx = b * 256 + tid;

    int v = 0;
    if (idx < NN) {
        v = g_deg[idx];
        g_deg[idx] = 0;
        g_dis[idx] = rsqrtf((float)(v + 1));
    }
    sh[tid] = v;
    __syncthreads();
#pragma unroll
    for (int o = 1; o < 256; o <<= 1) {
        int t2 = (tid >= o) ? sh[tid - o] : 0;
        __syncthreads();
        sh[tid] += t2;
        __syncthreads();
    }
    const int incl = sh[tid];
    const int total = sh[255];

    if (tid == 0) {
        s_prefix = 0;
        __threadfence();
        atomicExch(&g_pub[b], total | FLAG_BIT);
        if (b == 0) g_off[NN] = E;
    }
    __syncthreads();

    if (tid < b) {
        int p;
        do { p = atomicAdd(&g_pub[tid], 0); } while (!(p & FLAG_BIT));
        atomicAdd(&s_prefix, p & ~FLAG_BIT);
    }
    __syncthreads();

    if (idx < NN) {
        const int off = s_prefix + incl - v;
        g_off[idx] = off;
        g_cur[idx] = off;
    }
}

__global__ __launch_bounds__(256) void fill_k(const int* __restrict__ ei, int E) {
    const int t = blockIdx.x * 256 + threadIdx.x;
    const int e4 = t * 4;
    if (e4 + 4 <= E) {
        const int4 r = __ldg((const int4*)ei + t);
        const int4 c = __ldg((const int4*)(ei + E) + t);
        int p0 = atomicAdd(&g_cur[c.x], 1);
        int p1 = atomicAdd(&g_cur[c.y], 1);
        int p2 = atomicAdd(&g_cur[c.z], 1);
        int p3 = atomicAdd(&g_cur[c.w], 1);
        g_edge[p0] = (unsigned long long)(unsigned int)r.x |
                     ((unsigned long long)__float_as_uint(g_dis[r.x] * g_dis[c.x]) << 32);
        g_edge[p1] = (unsigned long long)(unsigned int)r.y |
                     ((unsigned long long)__float_as_uint(g_dis[r.y] * g_dis[c.y]) << 32);
        g_edge[p2] = (unsigned long long)(unsigned int)r.z |
                     ((unsigned long long)__float_as_uint(g_dis[r.z] * g_dis[c.z]) << 32);
        g_edge[p3] = (unsigned long long)(unsigned int)r.w |
                     ((unsigned long long)__float_as_uint(g_dis[r.w] * g_dis[c.w]) << 32);
    } else {
        for (int e = e4; e < E; e++) {
            const int r = ei[e], c = ei[E + e];
            const int pos = atomicAdd(&g_cur[c], 1);
            g_edge[pos] = (unsigned long long)(unsigned int)r |
                          ((unsigned long long)__float_as_uint(g_dis[r] * g_dis[c]) << 32);
        }
    }
}

// ---------------------------------------------------------------------------
// Tensor-core GEMM: 128 rows x 64 cols per 256-thread block (8 warps,
// 16 rows/warp), mma.sync m16n8k16 fp16 in / fp32 accum.
// MODE 0: x fp32 (B,N,D). MODE 1: x = g_h1h fp16. Output: g_xwh fp16.
// ---------------------------------------------------------------------------
template <int MODE>
__device__ __forceinline__ void gemm_body(const float* __restrict__ x,
                                          const float* __restrict__ W,
                                          int blk) {
    __shared__ __align__(16) __half As[128 * AP];   // 18.4 KB
    __shared__ __align__(16) __half Wsh[64 * AP];   // 9.2 KB
    const int tid  = threadIdx.x;
    const int warp = tid >> 5;
    const int lane = tid & 31;

    {
        const float4* W4 = (const float4*)W;
#pragma unroll
        for (int i = 0; i < 4; i++) {
            const int q = i * 256 + tid;
            const int row = q >> 4, c4 = q & 15;
            const float4 v = __ldg(W4 + q);
            *(__half2*)&Wsh[row * AP + c4 * 4]     = __floats2half2_rn(v.x, v.y);
            *(__half2*)&Wsh[row * AP + c4 * 4 + 2] = __floats2half2_rn(v.z, v.w);
        }
    }

    const int base = blk * 128;
    if (MODE == 0) {
#pragma unroll
        for (int i = 0; i < 8; i++) {
            const int q = i * 256 + tid;
            const int row = q >> 4, c4 = q & 15;
            int rr = base + row; if (rr >= NR) rr = NR - 1;
            const int n = rr >> 2, bb = rr & 3;
            const float4 v = __ldg((const float4*)(x + ((size_t)bb * NN + n) * DD) + c4);
            *(__half2*)&As[row * AP + c4 * 4]     = __floats2half2_rn(v.x, v.y);
            *(__half2*)&As[row * AP + c4 * 4 + 2] = __floats2half2_rn(v.z, v.w);
        }
    } else {
#pragma unroll
        for (int i = 0; i < 4; i++) {
            const int q = i * 256 + tid;
            const int row = q >> 3, u4 = q & 7;
            int rr = base + row; if (rr >= NR) rr = NR - 1;
            const uint4 u = __ldg(&g_h1h[(size_t)rr * 8 + u4]);
            *(uint4*)&As[row * AP + u4 * 8] = u;
        }
    }
    __syncthreads();

    float acc[8][4];
#pragma unroll
    for (int t = 0; t < 8; t++)
#pragma unroll
        for (int r = 0; r < 4; r++) acc[t][r] = 0.0f;

#pragma unroll
    for (int k0 = 0; k0 < 64; k0 += 16) {
        unsigned a0, a1, a2, a3;
        {
            const int arow = warp * 16 + (lane & 15);
            const int acol = k0 + ((lane >> 4) << 3);
            const unsigned addrA = smem_u32(&As[arow * AP + acol]);
            asm volatile(
                "ldmatrix.sync.aligned.m8n8.x4.shared.b16 {%0,%1,%2,%3}, [%4];"
                : "=r"(a0), "=r"(a1), "=r"(a2), "=r"(a3) : "r"(addrA));
        }
#pragma unroll
        for (int nt = 0; nt < 8; nt += 2) {
            unsigned b0, b1, b2, b3;
            {
                const int l8  = lane & 7;
                const int sel = lane >> 3;
                const int brow = k0 + l8 + ((sel & 1) << 3);
                const int bcol = (nt + (sel >> 1)) * 8;
                const unsigned addrB = smem_u32(&Wsh[brow * AP + bcol]);
                asm volatile(
                    "ldmatrix.sync.aligned.m8n8.x4.trans.shared.b16 {%0,%1,%2,%3}, [%4];"
                    : "=r"(b0), "=r"(b1), "=r"(b2), "=r"(b3) : "r"(addrB));
            }
            asm volatile(
                "mma.sync.aligned.m16n8k16.row.col.f32.f16.f16.f32 "
                "{%0,%1,%2,%3}, {%4,%5,%6,%7}, {%8,%9}, {%0,%1,%2,%3};"
                : "+f"(acc[nt][0]), "+f"(acc[nt][1]), "+f"(acc[nt][2]), "+f"(acc[nt][3])
                : "r"(a0), "r"(a1), "r"(a2), "r"(a3), "r"(b0), "r"(b1));
            asm volatile(
                "mma.sync.aligned.m16n8k16.row.col.f32.f16.f16.f32 "
                "{%0,%1,%2,%3}, {%4,%5,%6,%7}, {%8,%9}, {%0,%1,%2,%3};"
                : "+f"(acc[nt + 1][0]), "+f"(acc[nt + 1][1]), "+f"(acc[nt + 1][2]), "+f"(acc[nt + 1][3])
                : "r"(a0), "r"(a1), "r"(a2), "r"(a3), "r"(b2), "r"(b3));
        }
    }

    {
        __half* xwp = (__half*)g_xwh;
        const int g   = lane >> 2;
        const int tig = lane & 3;
        const int row_lo = base + warp * 16 + g;
        const int row_hi = row_lo + 8;
        if (row_lo < NR) {
            __half* p = xwp + (size_t)row_lo * 64 + tig * 2;
#pragma unroll
            for (int nt = 0; nt < 8; nt++)
                *(__half2*)(p + nt * 8) = __floats2half2_rn(acc[nt][0], acc[nt][1]);
        }
        if (row_hi < NR) {
            __half* p = xwp + (size_t)row_hi * 64 + tig * 2;
#pragma unroll
            for (int nt = 0; nt < 8; nt++)
                *(__half2*)(p + nt * 8) = __floats2half2_rn(acc[nt][2], acc[nt][3]);
        }
    }
}

// fused: gemm1 blocks [0, GEMM_B) + degree-count blocks [GEMM_B, GEMM_B+cB)
// (independent work — gemm1 depends only on h/W1, count only on edge_index)
__global__ __launch_bounds__(256) void gemmcount_k(const float* __restrict__ x,
                                                   const float* __restrict__ W,
                                                   const int* __restrict__ ei, int E) {
    if (blockIdx.x < GEMM_B) gemm_body<0>(x, W, blockIdx.x);
    else                     count_body(ei, E, blockIdx.x - GEMM_B);
}

__global__ __launch_bounds__(256) void gemm2_k(const float* __restrict__ W) {
    gemm_body<1>(nullptr, W, blockIdx.x);
}

// ---------------------------------------------------------------------------
// Aggregation: warp per node; lane owns uint4 slice `lane` (8 halfs).
// ---------------------------------------------------------------------------
__device__ __forceinline__ void fma_u4(float* A, const uint4 u, const float nm) {
    const __half2* hp = (const __half2*)&u;
    const float2 f0 = __half22float2(hp[0]);
    const float2 f1 = __half22float2(hp[1]);
    const float2 f2 = __half22float2(hp[2]);
    const float2 f3 = __half22float2(hp[3]);
    A[0] = fmaf(f0.x, nm, A[0]); A[1] = fmaf(f0.y, nm, A[1]);
    A[2] = fmaf(f1.x, nm, A[2]); A[3] = fmaf(f1.y, nm, A[3]);
    A[4] = fmaf(f2.x, nm, A[4]); A[5] = fmaf(f2.y, nm, A[5]);
    A[6] = fmaf(f3.x, nm, A[6]); A[7] = fmaf(f3.y, nm, A[7]);
}

template <bool FINAL>
__global__ __launch_bounds__(256) void agg_k(const float* __restrict__ bias,
                                             float* __restrict__ dst) {
    const int node = blockIdx.x * 8 + (threadIdx.x >> 5);
    const int lane = threadIdx.x & 31;
    if (node >= NN) return;

    const uint4* __restrict__ xw = g_xwh;
    float A[8];

    {
        const float dn = g_dis[node];
        const float sl = dn * dn;
        const uint4 u = __ldg(xw + (size_t)node * 32 + lane);
        const __half2* hp = (const __half2*)&u;
        const float2 f0 = __half22float2(hp[0]);
        const float2 f1 = __half22float2(hp[1]);
        const float2 f2 = __half22float2(hp[2]);
        const float2 f3 = __half22float2(hp[3]);
        A[0] = f0.x * sl; A[1] = f0.y * sl;
        A[2] = f1.x * sl; A[3] = f1.y * sl;
        A[4] = f2.x * sl; A[5] = f2.y * sl;
        A[6] = f3.x * sl; A[7] = f3.y * sl;
    }

    int j = g_off[node];
    const int end = g_off[node + 1];

    unsigned long long e0 = 0, e1 = 0, e2 = 0, e3 = 0;
    if (j + 4 <= end) {
        e0 = __ldg(g_edge + j);
        e1 = __ldg(g_edge + j + 1);
        e2 = __ldg(g_edge + j + 2);
        e3 = __ldg(g_edge + j + 3);
    }
    while (j + 8 <= end) {
        const unsigned long long f0 = __ldg(g_edge + j + 4);
        const unsigned long long f1 = __ldg(g_edge + j + 5);
        const unsigned long long f2 = __ldg(g_edge + j + 6);
        const unsigned long long f3 = __ldg(g_edge + j + 7);
        const uint4 v0 = __ldg(xw + (size_t)(unsigned int)(e0 & 0xffffffffu) * 32 + lane);
        const uint4 v1 = __ldg(xw + (size_t)(unsigned int)(e1 & 0xffffffffu) * 32 + lane);
        const uint4 v2 = __ldg(xw + (size_t)(unsigned int)(e2 & 0xffffffffu) * 32 + lane);
        const uint4 v3 = __ldg(xw + (size_t)(unsigned int)(e3 & 0xffffffffu) * 32 + lane);
        fma_u4(A, v0, __uint_as_float((unsigned int)(e0 >> 32)));
        fma_u4(A, v1, __uint_as_float((unsigned int)(e1 >> 32)));
        fma_u4(A, v2, __uint_as_float((unsigned int)(e2 >> 32)));
        fma_u4(A, v3, __uint_as_float((unsigned int)(e3 >> 32)));
        e0 = f0; e1 = f1; e2 = f2; e3 = f3;
        j += 4;
    }
    if (j + 4 <= end) {
        const uint4 v0 = __ldg(xw + (size_t)(unsigned int)(e0 & 0xffffffffu) * 32 + lane);
        const uint4 v1 = __ldg(xw + (size_t)(unsigned int)(e1 & 0xffffffffu) * 32 + lane);
        const uint4 v2 = __ldg(xw + (size_t)(unsigned int)(e2 & 0xffffffffu) * 32 + lane);
        const uint4 v3 = __ldg(xw + (size_t)(unsigned int)(e3 & 0xffffffffu) * 32 + lane);
        fma_u4(A, v0, __uint_as_float((unsigned int)(e0 >> 32)));
        fma_u4(A, v1, __uint_as_float((unsigned int)(e1 >> 32)));
        fma_u4(A, v2, __uint_as_float((unsigned int)(e2 >> 32)));
        fma_u4(A, v3, __uint_as_float((unsigned int)(e3 >> 32)));
        j += 4;
    }
    {
        const int rem = end - j;
        if (rem > 0) {
            const unsigned long long t0 = __ldg(g_edge + j);
            const unsigned long long t1 = (rem > 1) ? __ldg(g_edge + j + 1) : 0;
            const unsigned long long t2 = (rem > 2) ? __ldg(g_edge + j + 2) : 0;
            const uint4 v0 = __ldg(xw + (size_t)(unsigned int)(t0 & 0xffffffffu) * 32 + lane);
            fma_u4(A, v0, __uint_as_float((unsigned int)(t0 >> 32)));
            if (rem > 1) {
                const uint4 v1 = __ldg(xw + (size_t)(unsigned int)(t1 & 0xffffffffu) * 32 + lane);
                fma_u4(A, v1, __uint_as_float((unsigned int)(t1 >> 32)));
            }
            if (rem > 2) {
                const uint4 v2 = __ldg(xw + (size_t)(unsigned int)(t2 & 0xffffffffu) * 32 + lane);
                fma_u4(A, v2, __uint_as_float((unsigned int)(t2 >> 32)));
            }
        }
    }

    const float4 bv0 = __ldg((const float4*)bias + (lane & 7) * 2);
    const float4 bv1 = __ldg((const float4*)bias + (lane & 7) * 2 + 1);
    float o[8];
    o[0] = tanhf(A[0] + bv0.x); o[1] = tanhf(A[1] + bv0.y);
    o[2] = tanhf(A[2] + bv0.z); o[3] = tanhf(A[3] + bv0.w);
    o[4] = tanhf(A[4] + bv1.x); o[5] = tanhf(A[5] + bv1.y);
    o[6] = tanhf(A[6] + bv1.z); o[7] = tanhf(A[7] + bv1.w);

    if (FINAL) {
        const int b = lane >> 3;
        float4* o4 = (float4*)dst + ((size_t)b * NN + node) * 16 + (lane & 7) * 2;
        o4[0] = make_float4(o[0], o[1], o[2], o[3]);
        o4[1] = make_float4(o[4], o[5], o[6], o[7]);
    } else {
        const __half2 p0 = __floats2half2_rn(o[0], o[1]);
        const __half2 p1 = __floats2half2_rn(o[2], o[3]);
        const __half2 p2 = __floats2half2_rn(o[4], o[5]);
        const __half2 p3 = __floats2half2_rn(o[6], o[7]);
        uint4 u;
        u.x = *(const unsigned int*)&p0;
        u.y = *(const unsigned int*)&p1;
        u.z = *(const unsigned int*)&p2;
        u.w = *(const unsigned int*)&p3;
        g_h1h[(size_t)node * 32 + lane] = u;
    }
}

// ---------------------------------------------------------------------------
extern "C" void kernel_launch(void* const* d_in, const int* in_sizes, int n_in,
                              void* d_out, int out_size) {
    const float* h  = (const float*)d_in[1];
    const int*   ei = (const int*)d_in[2];
    const float* W1 = (const float*)d_in[3];
    const float* b1 = (const float*)d_in[4];
    const float* W2 = (const float*)d_in[5];
    const float* b2 = (const float*)d_in[6];
    float* out = (float*)d_out;

    const int E  = in_sizes[2] / 2;
    const int cB = (E / 4 + 255) / 256 + 1;
    const int aB = (NN + 7) / 8;

    gemmcount_k<<<GEMM_B + cB, 256>>>(h, W1, ei, E);  // 1 (gemm1 || count)
    scan_k <<<SCAN_B, 256>>>(E);                      // 2
    fill_k <<<cB, 256>>>(ei, E);                      // 3
    agg_k<false><<<aB, 256>>>(b1, nullptr);           // 4  <- profiled
    gemm2_k<<<GEMM_B, 256>>>(W2);                     // 5
    agg_k<true> <<<aB, 256>>>(b2, out);               // 6
}

// round 10
// speedup vs baseline: 5.9772x; 1.0317x over previous
#include <cuda_runtime.h>
#include <cuda_fp16.h>
#include <math.h>

// Fixed-shape problem: B=4, N=50000, E=800000, D=64
#define NN 50000
#define BB 4
#define DD 64
#define NR (NN * BB)                 // 200000 rows (node-major: row = node*4 + b)
#define SCAN_B 196                   // ceil(50000/256)
#define GEMM_B ((NR + 127) / 128)    // 1563 blocks
#define FLAG_BIT 0x40000000
#define AP 72                        // padded smem row stride (halfs) = 144 B

// Scratch (__device__ globals per allocation-free rule)
__device__ uint4  g_xwh[(size_t)NR * 8];        // linear output, fp16, 25.6 MB
__device__ uint4  g_h1h[(size_t)NR * 8];        // layer-1 activation, fp16, 25.6 MB
__device__ float  g_dis[NN];                    // rsqrt(deg+1)
__device__ int    g_deg[NN];                    // zero-init; re-zeroed each pass
__device__ int    g_off[NN + 1];                // CSR offsets (by target node)
__device__ int    g_cur[NN];                    // fill cursors
__device__ unsigned long long g_edge[800000];   // packed (src byte-offset, nrm fp32)
__device__ int    g_pub[SCAN_B];                // lookback publications

static __device__ __forceinline__ unsigned smem_u32(const void* p) {
    return (unsigned)__cvta_generic_to_shared(p);
}

// fast tanh: 1 - 2*rcp(ex2(x*2*log2e)+1); MUFU-based, rel err ~1e-6,
// saturates correctly at +/-inf.
static __device__ __forceinline__ float ftanh(float x) {
    float e;
    asm("ex2.approx.f32 %0, %1;" : "=f"(e) : "f"(x * 2.885390082f));
    float r;
    asm("rcp.approx.f32 %0, %1;" : "=f"(r) : "f"(e + 1.0f));
    return fmaf(-2.0f, r, 1.0f);
}

// ---------------------------------------------------------------------------
// degree count (4 edges/thread) + scan-flag reset
// ---------------------------------------------------------------------------
__global__ __launch_bounds__(256) void count_k(const int* __restrict__ ei, int E) {
    const int t = blockIdx.x * 256 + threadIdx.x;
    if (blockIdx.x == 0 && threadIdx.x < SCAN_B) g_pub[threadIdx.x] = 0;
    const int e4 = t * 4;
    if (e4 + 4 <= E) {
        const int4 c = __ldg((const int4*)(ei + E) + t);
        atomicAdd(&g_deg[c.x], 1);
        atomicAdd(&g_deg[c.y], 1);
        atomicAdd(&g_deg[c.z], 1);
        atomicAdd(&g_deg[c.w], 1);
    } else {
        for (int e = e4; e < E; e++) atomicAdd(&g_deg[ei[E + e]], 1);
    }
}

// ---------------------------------------------------------------------------
// single-pass exclusive scan (decoupled lookback); emits g_dis, re-zeroes g_deg
// ---------------------------------------------------------------------------
__global__ __launch_bounds__(256) void scan_k(int E) {
    __shared__ int sh[256];
    __shared__ int s_prefix;
    const int tid = threadIdx.x;
    const int b   = blockIdx.x;
    const int idx = b * 256 + tid;

    int v = 0;
    if (idx < NN) {
        v = g_deg[idx];
        g_deg[idx] = 0;
        g_dis[idx] = rsqrtf((float)(v + 1));
    }
    sh[tid] = v;
    __syncthreads();
#pragma unroll
    for (int o = 1; o < 256; o <<= 1) {
        int t2 = (tid >= o) ? sh[tid - o] : 0;
        __syncthreads();
        sh[tid] += t2;
        __syncthreads();
    }
    const int incl = sh[tid];
    const int total = sh[255];

    if (tid == 0) {
        s_prefix = 0;
        __threadfence();
        atomicExch(&g_pub[b], total | FLAG_BIT);
        if (b == 0) g_off[NN] = E;
    }
    __syncthreads();

    if (tid < b) {
        int p;
        do { p = atomicAdd(&g_pub[tid], 0); } while (!(p & FLAG_BIT));
        atomicAdd(&s_prefix, p & ~FLAG_BIT);
    }
    __syncthreads();

    if (idx < NN) {
        const int off = s_prefix + incl - v;
        g_off[idx] = off;
        g_cur[idx] = off;
    }
}

// ---------------------------------------------------------------------------
// fill body: CSR records. Low word = src node BYTE offset into feature table
// (src*512); high word = fp32 norm.
// ---------------------------------------------------------------------------
__device__ __forceinline__ void fill_body(const int* __restrict__ ei, int E, int blk) {
    const int t = blk * 256 + threadIdx.x;
    const int e4 = t * 4;
    if (e4 + 4 <= E) {
        const int4 r = __ldg((const int4*)ei + t);
        const int4 c = __ldg((const int4*)(ei + E) + t);
        int p0 = atomicAdd(&g_cur[c.x], 1);
        int p1 = atomicAdd(&g_cur[c.y], 1);
        int p2 = atomicAdd(&g_cur[c.z], 1);
        int p3 = atomicAdd(&g_cur[c.w], 1);
        g_edge[p0] = (unsigned long long)((unsigned)r.x * 512u) |
                     ((unsigned long long)__float_as_uint(g_dis[r.x] * g_dis[c.x]) << 32);
        g_edge[p1] = (unsigned long long)((unsigned)r.y * 512u) |
                     ((unsigned long long)__float_as_uint(g_dis[r.y] * g_dis[c.y]) << 32);
        g_edge[p2] = (unsigned long long)((unsigned)r.z * 512u) |
                     ((unsigned long long)__float_as_uint(g_dis[r.z] * g_dis[c.z]) << 32);
        g_edge[p3] = (unsigned long long)((unsigned)r.w * 512u) |
                     ((unsigned long long)__float_as_uint(g_dis[r.w] * g_dis[c.w]) << 32);
    } else {
        for (int e = e4; e < E; e++) {
            const int r = ei[e], c = ei[E + e];
            const int pos = atomicAdd(&g_cur[c], 1);
            g_edge[pos] = (unsigned long long)((unsigned)r * 512u) |
                          ((unsigned long long)__float_as_uint(g_dis[r] * g_dis[c]) << 32);
        }
    }
}

// ---------------------------------------------------------------------------
// Tensor-core GEMM: 128 rows x 64 cols per 256-thread block (8 warps,
// 16 rows/warp), mma.sync m16n8k16 fp16 in / fp32 accum.
// MODE 0: x fp32 (B,N,D). MODE 1: x = g_h1h fp16. Output: g_xwh fp16.
// ---------------------------------------------------------------------------
template <int MODE>
__device__ __forceinline__ void gemm_body(const float* __restrict__ x,
                                          const float* __restrict__ W,
                                          int blk) {
    __shared__ __align__(16) __half As[128 * AP];   // 18.4 KB
    __shared__ __align__(16) __half Wsh[64 * AP];   // 9.2 KB
    const int tid  = threadIdx.x;
    const int warp = tid >> 5;
    const int lane = tid & 31;

    {
        const float4* W4 = (const float4*)W;
#pragma unroll
        for (int i = 0; i < 4; i++) {
            const int q = i * 256 + tid;
            const int row = q >> 4, c4 = q & 15;
            const float4 v = __ldg(W4 + q);
            *(__half2*)&Wsh[row * AP + c4 * 4]     = __floats2half2_rn(v.x, v.y);
            *(__half2*)&Wsh[row * AP + c4 * 4 + 2] = __floats2half2_rn(v.z, v.w);
        }
    }

    const int base = blk * 128;
    if (MODE == 0) {
#pragma unroll
        for (int i = 0; i < 8; i++) {
            const int q = i * 256 + tid;
            const int row = q >> 4, c4 = q & 15;
            int rr = base + row; if (rr >= NR) rr = NR - 1;
            const int n = rr >> 2, bb = rr & 3;
            const float4 v = __ldg((const float4*)(x + ((size_t)bb * NN + n) * DD) + c4);
            *(__half2*)&As[row * AP + c4 * 4]     = __floats2half2_rn(v.x, v.y);
            *(__half2*)&As[row * AP + c4 * 4 + 2] = __floats2half2_rn(v.z, v.w);
        }
    } else {
#pragma unroll
        for (int i = 0; i < 4; i++) {
            const int q = i * 256 + tid;
            const int row = q >> 3, u4 = q & 7;
            int rr = base + row; if (rr >= NR) rr = NR - 1;
            const uint4 u = __ldg(&g_h1h[(size_t)rr * 8 + u4]);
            *(uint4*)&As[row * AP + u4 * 8] = u;
        }
    }
    __syncthreads();

    float acc[8][4];
#pragma unroll
    for (int t = 0; t < 8; t++)
#pragma unroll
        for (int r = 0; r < 4; r++) acc[t][r] = 0.0f;

#pragma unroll
    for (int k0 = 0; k0 < 64; k0 += 16) {
        unsigned a0, a1, a2, a3;
        {
            const int arow = warp * 16 + (lane & 15);
            const int acol = k0 + ((lane >> 4) << 3);
            const unsigned addrA = smem_u32(&As[arow * AP + acol]);
            asm volatile(
                "ldmatrix.sync.aligned.m8n8.x4.shared.b16 {%0,%1,%2,%3}, [%4];"
                : "=r"(a0), "=r"(a1), "=r"(a2), "=r"(a3) : "r"(addrA));
        }
#pragma unroll
        for (int nt = 0; nt < 8; nt += 2) {
            unsigned b0, b1, b2, b3;
            {
                const int l8  = lane & 7;
                const int sel = lane >> 3;
                const int brow = k0 + l8 + ((sel & 1) << 3);
                const int bcol = (nt + (sel >> 1)) * 8;
                const unsigned addrB = smem_u32(&Wsh[brow * AP + bcol]);
                asm volatile(
                    "ldmatrix.sync.aligned.m8n8.x4.trans.shared.b16 {%0,%1,%2,%3}, [%4];"
                    : "=r"(b0), "=r"(b1), "=r"(b2), "=r"(b3) : "r"(addrB));
            }
            asm volatile(
                "mma.sync.aligned.m16n8k16.row.col.f32.f16.f16.f32 "
                "{%0,%1,%2,%3}, {%4,%5,%6,%7}, {%8,%9}, {%0,%1,%2,%3};"
                : "+f"(acc[nt][0]), "+f"(acc[nt][1]), "+f"(acc[nt][2]), "+f"(acc[nt][3])
                : "r"(a0), "r"(a1), "r"(a2), "r"(a3), "r"(b0), "r"(b1));
            asm volatile(
                "mma.sync.aligned.m16n8k16.row.col.f32.f16.f16.f32 "
                "{%0,%1,%2,%3}, {%4,%5,%6,%7}, {%8,%9}, {%0,%1,%2,%3};"
                : "+f"(acc[nt + 1][0]), "+f"(acc[nt + 1][1]), "+f"(acc[nt + 1][2]), "+f"(acc[nt + 1][3])
                : "r"(a0), "r"(a1), "r"(a2), "r"(a3), "r"(b2), "r"(b3));
        }
    }

    {
        __half* xwp = (__half*)g_xwh;
        const int g   = lane >> 2;
        const int tig = lane & 3;
        const int row_lo = base + warp * 16 + g;
        const int row_hi = row_lo + 8;
        if (row_lo < NR) {
            __half* p = xwp + (size_t)row_lo * 64 + tig * 2;
#pragma unroll
            for (int nt = 0; nt < 8; nt++)
                *(__half2*)(p + nt * 8) = __floats2half2_rn(acc[nt][0], acc[nt][1]);
        }
        if (row_hi < NR) {
            __half* p = xwp + (size_t)row_hi * 64 + tig * 2;
#pragma unroll
            for (int nt = 0; nt < 8; nt++)
                *(__half2*)(p + nt * 8) = __floats2half2_rn(acc[nt][2], acc[nt][3]);
        }
    }
}

// fused: gemm1 blocks [0, GEMM_B) + CSR-fill blocks [GEMM_B, ...)
// (independent work — gemm1 depends only on h/W1; fill depends on scan)
__global__ __launch_bounds__(256) void gemmfill_k(const float* __restrict__ x,
                                                  const float* __restrict__ W,
                                                  const int* __restrict__ ei, int E) {
    if (blockIdx.x < GEMM_B) gemm_body<0>(x, W, blockIdx.x);
    else                     fill_body(ei, E, blockIdx.x - GEMM_B);
}

__global__ __launch_bounds__(256) void gemm2_k(const float* __restrict__ W) {
    gemm_body<1>(nullptr, W, blockIdx.x);
}

// ---------------------------------------------------------------------------
// Aggregation: warp per node; lane owns uint4 slice `lane` (8 halfs).
// Edge records carry byte offsets; value address = table + off + lane*16.
// ---------------------------------------------------------------------------
__device__ __forceinline__ void fma_u4(float* A, const uint4 u, const float nm) {
    const __half2* hp = (const __half2*)&u;
    const float2 f0 = __half22float2(hp[0]);
    const float2 f1 = __half22float2(hp[1]);
    const float2 f2 = __half22float2(hp[2]);
    const float2 f3 = __half22float2(hp[3]);
    A[0] = fmaf(f0.x, nm, A[0]); A[1] = fmaf(f0.y, nm, A[1]);
    A[2] = fmaf(f1.x, nm, A[2]); A[3] = fmaf(f1.y, nm, A[3]);
    A[4] = fmaf(f2.x, nm, A[4]); A[5] = fmaf(f2.y, nm, A[5]);
    A[6] = fmaf(f3.x, nm, A[6]); A[7] = fmaf(f3.y, nm, A[7]);
}

template <bool FINAL>
__global__ __launch_bounds__(256) void agg_k(const float* __restrict__ bias,
                                             float* __restrict__ dst) {
    const int node = blockIdx.x * 8 + (threadIdx.x >> 5);
    const int lane = threadIdx.x & 31;
    if (node >= NN) return;

    // per-lane base pointer into the fp16 feature table
    const char* __restrict__ xwb = (const char*)g_xwh + (unsigned)lane * 16u;
    float A[8];

    {
        const float dn = g_dis[node];
        const float sl = dn * dn;
        const uint4 u = __ldg((const uint4*)(xwb + (unsigned)node * 512u));
        const __half2* hp = (const __half2*)&u;
        const float2 f0 = __half22float2(hp[0]);
        const float2 f1 = __half22float2(hp[1]);
        const float2 f2 = __half22float2(hp[2]);
        const float2 f3 = __half22float2(hp[3]);
        A[0] = f0.x * sl; A[1] = f0.y * sl;
        A[2] = f1.x * sl; A[3] = f1.y * sl;
        A[4] = f2.x * sl; A[5] = f2.y * sl;
        A[6] = f3.x * sl; A[7] = f3.y * sl;
    }

    int j = g_off[node];
    const int end = g_off[node + 1];

    unsigned long long e0 = 0, e1 = 0, e2 = 0, e3 = 0;
    if (j + 4 <= end) {
        e0 = __ldg(g_edge + j);
        e1 = __ldg(g_edge + j + 1);
        e2 = __ldg(g_edge + j + 2);
        e3 = __ldg(g_edge + j + 3);
    }
    while (j + 8 <= end) {
        const unsigned long long f0 = __ldg(g_edge + j + 4);
        const unsigned long long f1 = __ldg(g_edge + j + 5);
        const unsigned long long f2 = __ldg(g_edge + j + 6);
        const unsigned long long f3 = __ldg(g_edge + j + 7);
        const uint4 v0 = __ldg((const uint4*)(xwb + (unsigned)e0));
        const uint4 v1 = __ldg((const uint4*)(xwb + (unsigned)e1));
        const uint4 v2 = __ldg((const uint4*)(xwb + (unsigned)e2));
        const uint4 v3 = __ldg((const uint4*)(xwb + (unsigned)e3));
        fma_u4(A, v0, __uint_as_float((unsigned)(e0 >> 32)));
        fma_u4(A, v1, __uint_as_float((unsigned)(e1 >> 32)));
        fma_u4(A, v2, __uint_as_float((unsigned)(e2 >> 32)));
        fma_u4(A, v3, __uint_as_float((unsigned)(e3 >> 32)));
        e0 = f0; e1 = f1; e2 = f2; e3 = f3;
        j += 4;
    }
    if (j + 4 <= end) {
        const uint4 v0 = __ldg((const uint4*)(xwb + (unsigned)e0));
        const uint4 v1 = __ldg((const uint4*)(xwb + (unsigned)e1));
        const uint4 v2 = __ldg((const uint4*)(xwb + (unsigned)e2));
        const uint4 v3 = __ldg((const uint4*)(xwb + (unsigned)e3));
        fma_u4(A, v0, __uint_as_float((unsigned)(e0 >> 32)));
        fma_u4(A, v1, __uint_as_float((unsigned)(e1 >> 32)));
        fma_u4(A, v2, __uint_as_float((unsigned)(e2 >> 32)));
        fma_u4(A, v3, __uint_as_float((unsigned)(e3 >> 32)));
        j += 4;
    }
    {
        const int rem = end - j;
        if (rem > 0) {
            const unsigned long long t0 = __ldg(g_edge + j);
            const unsigned long long t1 = (rem > 1) ? __ldg(g_edge + j + 1) : 0;
            const unsigned long long t2 = (rem > 2) ? __ldg(g_edge + j + 2) : 0;
            const uint4 v0 = __ldg((const uint4*)(xwb + (unsigned)t0));
            fma_u4(A, v0, __uint_as_float((unsigned)(t0 >> 32)));
            if (rem > 1) {
                const uint4 v1 = __ldg((const uint4*)(xwb + (unsigned)t1));
                fma_u4(A, v1, __uint_as_float((unsigned)(t1 >> 32)));
            }
            if (rem > 2) {
                const uint4 v2 = __ldg((const uint4*)(xwb + (unsigned)t2));
                fma_u4(A, v2, __uint_as_float((unsigned)(t2 >> 32)));
            }
        }
    }

    const float4 bv0 = __ldg((const float4*)bias + (lane & 7) * 2);
    const float4 bv1 = __ldg((const float4*)bias + (lane & 7) * 2 + 1);
    float o[8];
    o[0] = ftanh(A[0] + bv0.x); o[1] = ftanh(A[1] + bv0.y);
    o[2] = ftanh(A[2] + bv0.z); o[3] = ftanh(A[3] + bv0.w);
    o[4] = ftanh(A[4] + bv1.x); o[5] = ftanh(A[5] + bv1.y);
    o[6] = ftanh(A[6] + bv1.z); o[7] = ftanh(A[7] + bv1.w);

    if (FINAL) {
        const int b = lane >> 3;
        float4* o4 = (float4*)dst + ((size_t)b * NN + node) * 16 + (lane & 7) * 2;
        o4[0] = make_float4(o[0], o[1], o[2], o[3]);
        o4[1] = make_float4(o[4], o[5], o[6], o[7]);
    } else {
        const __half2 p0 = __floats2half2_rn(o[0], o[1]);
        const __half2 p1 = __floats2half2_rn(o[2], o[3]);
        const __half2 p2 = __floats2half2_rn(o[4], o[5]);
        const __half2 p3 = __floats2half2_rn(o[6], o[7]);
        uint4 u;
        u.x = *(const unsigned int*)&p0;
        u.y = *(const unsigned int*)&p1;
        u.z = *(const unsigned int*)&p2;
        u.w = *(const unsigned int*)&p3;
        g_h1h[(size_t)node * 32 + lane] = u;
    }
}

// ---------------------------------------------------------------------------
extern "C" void kernel_launch(void* const* d_in, const int* in_sizes, int n_in,
                              void* d_out, int out_size) {
    const float* h  = (const float*)d_in[1];
    const int*   ei = (const int*)d_in[2];
    const float* W1 = (const float*)d_in[3];
    const float* b1 = (const float*)d_in[4];
    const float* W2 = (const float*)d_in[5];
    const float* b2 = (const float*)d_in[6];
    float* out = (float*)d_out;

    const int E  = in_sizes[2] / 2;
    const int cB = (E / 4 + 255) / 256 + 1;
    const int aB = (NN + 7) / 8;

    count_k<<<cB, 256>>>(ei, E);                      // 1
    scan_k <<<SCAN_B, 256>>>(E);                      // 2
    gemmfill_k<<<GEMM_B + cB, 256>>>(h, W1, ei, E);   // 3 (gemm1 || fill)
    agg_k<false><<<aB, 256>>>(b1, nullptr);           // 4  <- profiled
    gemm2_k<<<GEMM_B, 256>>>(W2);                     // 5
    agg_k<true> <<<aB, 256>>>(b2, out);               // 6
}